// round 11
// baseline (speedup 1.0000x reference)
#include <cuda_runtime.h>
#include <cuda_bf16.h>
#include <cuda_fp16.h>
#include <cstdint>

// ---------------------------------------------------------------------------
// AttentionModule via mma.sync m16n8k16 (legacy HMMA; tcgen05 ptxas-gated off).
// f32-accum HMMA measured at rt=14 cyc/SMSP (585 MACs/cyc/SM) — rate-capped.
// This round: f16-ACCUM HMMA (hypothesis: rt=7, 2x) for the pure-f16 GEMMs,
// with windowed f16->f32 flush every 8 K-chunks to bound rounding error.
//   q/k projections: bf16 split-3;  energy: bf16 split-3, f32 out
//   v projection:    1-pass f16 (Wv f16 x Vt f16), f16-accum windowed
//   out:             1-pass f16 (v x attn f16), f16-accum windowed, gamma*acc+V
// ---------------------------------------------------------------------------

static const int B_ = 4, C_ = 512, CH_ = 256, N_ = 4096;

__device__ __align__(256) __nv_bfloat16 g_Qt_h[4L * 4096 * 512];
__device__ __align__(256) __nv_bfloat16 g_Qt_l[4L * 4096 * 512];
__device__ __align__(256) __nv_bfloat16 g_Kt_h[4L * 4096 * 512];
__device__ __align__(256) __nv_bfloat16 g_Kt_l[4L * 4096 * 512];
__device__ __align__(256) __half        g_Vt  [4L * 4096 * 512];
__device__ __align__(256) __nv_bfloat16 g_Wq_h[256 * 512];
__device__ __align__(256) __nv_bfloat16 g_Wq_l[256 * 512];
__device__ __align__(256) __nv_bfloat16 g_Wk_h[256 * 512];
__device__ __align__(256) __nv_bfloat16 g_Wk_l[256 * 512];
__device__ __align__(256) __half        g_Wv  [512 * 512];
__device__ __align__(256) __nv_bfloat16 g_qt_h[4L * 4096 * 256];
__device__ __align__(256) __nv_bfloat16 g_qt_l[4L * 4096 * 256];
__device__ __align__(256) __nv_bfloat16 g_kt_h[4L * 4096 * 256];
__device__ __align__(256) __nv_bfloat16 g_kt_l[4L * 4096 * 256];
__device__ __align__(256) __half        g_v   [4L * 512 * 4096];
__device__ __align__(256) float         g_e   [4L * 4096 * 4096];
__device__ __align__(256) __half        g_a   [4L * 4096 * 4096];

__device__ __forceinline__ uint32_t smem_to_u32(const void* p) {
    uint32_t a;
    asm("{ .reg .u64 t; cvta.to.shared.u64 t, %1; cvt.u32.u64 %0, t; }" : "=r"(a) : "l"(p));
    return a;
}
__device__ __forceinline__ void cp16(uint32_t dst, const void* src) {
    asm volatile("cp.async.cg.shared.global [%0], [%1], 16;" :: "r"(dst), "l"(src) : "memory");
}
__device__ __forceinline__ void cp_commit() { asm volatile("cp.async.commit_group;" ::: "memory"); }
__device__ __forceinline__ void cp_wait1()  { asm volatile("cp.async.wait_group 1;" ::: "memory"); }
__device__ __forceinline__ void cp_wait0()  { asm volatile("cp.async.wait_group 0;" ::: "memory"); }

__device__ __forceinline__ void ldsm4(uint32_t* r, uint32_t a) {
    asm volatile("ldmatrix.sync.aligned.m8n8.x4.shared.b16 {%0,%1,%2,%3}, [%4];"
                 : "=r"(r[0]), "=r"(r[1]), "=r"(r[2]), "=r"(r[3]) : "r"(a));
}
__device__ __forceinline__ void mma_bf16(float* c, const uint32_t* a, const uint32_t* b) {
    asm volatile("mma.sync.aligned.m16n8k16.row.col.f32.bf16.bf16.f32 "
                 "{%0,%1,%2,%3}, {%4,%5,%6,%7}, {%8,%9}, {%0,%1,%2,%3};"
                 : "+f"(c[0]), "+f"(c[1]), "+f"(c[2]), "+f"(c[3])
                 : "r"(a[0]), "r"(a[1]), "r"(a[2]), "r"(a[3]), "r"(b[0]), "r"(b[1]));
}
__device__ __forceinline__ void mma_f16acc(uint32_t* d, const uint32_t* a, const uint32_t* b) {
    asm volatile("mma.sync.aligned.m16n8k16.row.col.f16.f16.f16.f16 "
                 "{%0,%1}, {%2,%3,%4,%5}, {%6,%7}, {%0,%1};"
                 : "+r"(d[0]), "+r"(d[1])
                 : "r"(a[0]), "r"(a[1]), "r"(a[2]), "r"(a[3]), "r"(b[0]), "r"(b[1]));
}

#define LDR     80
#define A_TILE  (128 * LDR)
#define B_TILE  (256 * LDR)

enum { F_SPLIT = 1, F_BROW = 2, F_BCOL = 4, F_RES = 8 };

// ---------------------------------------------------------------------------
// bf16 split-3 tgemm (q/k projections + energy). CTA 128x256, warp 64x64.
// ---------------------------------------------------------------------------
#define STAGE_S (2 * A_TILE + 2 * B_TILE)
#define TG_SMEM (2 * STAGE_S)

__global__ void __launch_bounds__(256, 1)
tgemm_kernel(const __nv_bfloat16* __restrict__ Ah, const __nv_bfloat16* __restrict__ Al,
             const __nv_bfloat16* __restrict__ Bh, const __nv_bfloat16* __restrict__ Bl,
             float* __restrict__ Cf, __nv_bfloat16* __restrict__ Chi, __nv_bfloat16* __restrict__ Clo,
             const float* __restrict__ bias,
             int Kd, int ldc, size_t sA, size_t sB, size_t sC, int flags)
{
    extern __shared__ char smem[];
    const uint32_t sm0 = smem_to_u32(smem);
    const int tid = threadIdx.x, wid = tid >> 5, lane = tid & 31;
    const int bz = blockIdx.z;
    const int m0 = blockIdx.y * 128;
    const int n0 = blockIdx.x * 256;

    const size_t ldkB = (size_t)Kd * 2;
    const int lr = tid >> 2, seg = tid & 3;
    const char* gA_h = (const char*)(Ah + (size_t)bz * sA) + (size_t)(m0 + lr) * ldkB + seg * 16;
    const char* gA_l = (const char*)(Al + (size_t)bz * sA) + (size_t)(m0 + lr) * ldkB + seg * 16;
    const char* gB_h = (const char*)(Bh + (size_t)bz * sB) + (size_t)(n0 + lr) * ldkB + seg * 16;
    const char* gB_l = (const char*)(Bl + (size_t)bz * sB) + (size_t)(n0 + lr) * ldkB + seg * 16;
    const size_t g64 = 64 * ldkB;
    const uint32_t dthr = sm0 + (uint32_t)lr * LDR + (uint32_t)seg * 16;

    const int nch = Kd >> 5;
    const int wm = wid & 1;
    const int wncol = (wid >> 1) * 64;
    const uint32_t a_off = (uint32_t)((lane & 15) * LDR + (lane >> 4) * 16);
    const uint32_t b_off = (uint32_t)(((lane & 7) + ((lane >> 4) & 1) * 8) * LDR + ((lane >> 3) & 1) * 16);

    float acc[4][8][4];
    #pragma unroll
    for (int i = 0; i < 4; i++)
        #pragma unroll
        for (int j = 0; j < 8; j++)
            #pragma unroll
            for (int k = 0; k < 4; k++) acc[i][j][k] = 0.f;

#define TG_LOAD(s, c) do { \
        const size_t _ko = (size_t)(c) * 64; \
        const uint32_t _d = dthr + (uint32_t)(s) * STAGE_S; \
        cp16(_d,                     gA_h + _ko); \
        cp16(_d + 64 * LDR,          gA_h + _ko + g64); \
        cp16(_d + A_TILE,            gA_l + _ko); \
        cp16(_d + A_TILE + 64 * LDR, gA_l + _ko + g64); \
        _Pragma("unroll") \
        for (int _j = 0; _j < 4; _j++) \
            cp16(_d + 2 * A_TILE + _j * 64 * LDR, gB_h + _ko + _j * g64); \
        _Pragma("unroll") \
        for (int _j = 0; _j < 4; _j++) \
            cp16(_d + 2 * A_TILE + B_TILE + _j * 64 * LDR, gB_l + _ko + _j * g64); \
        cp_commit(); \
    } while (0)

    TG_LOAD(0, 0);

    for (int c = 0; c < nch; c++) {
        const int s = c & 1;
        if (c + 1 < nch) { TG_LOAD(s ^ 1, c + 1); cp_wait1(); }
        else             { cp_wait0(); }
        __syncthreads();

        const uint32_t sb  = sm0 + (uint32_t)s * STAGE_S;
        const uint32_t sAh = sb, sAl = sb + A_TILE;
        const uint32_t sBh = sb + 2 * A_TILE, sBl = sBh + B_TILE;

        #pragma unroll
        for (int ks = 0; ks < 2; ks++) {
            const uint32_t ko = ks * 32;
            uint32_t bh[8][2], bl[8][2], af[4][4];
            #pragma unroll
            for (int p = 0; p < 4; p++) {
                uint32_t r[4];
                ldsm4(r, sBh + (uint32_t)(wncol + p * 16) * LDR + ko + b_off);
                bh[2 * p][0] = r[0]; bh[2 * p][1] = r[1];
                bh[2 * p + 1][0] = r[2]; bh[2 * p + 1][1] = r[3];
            }
            #pragma unroll
            for (int mt = 0; mt < 4; mt++)
                ldsm4(af[mt], sAh + (uint32_t)(wm * 64 + mt * 16) * LDR + ko + a_off);
            #pragma unroll
            for (int mt = 0; mt < 4; mt++)
                #pragma unroll
                for (int nt = 0; nt < 8; nt++) mma_bf16(acc[mt][nt], af[mt], bh[nt]);
            #pragma unroll
            for (int p = 0; p < 4; p++) {
                uint32_t r[4];
                ldsm4(r, sBl + (uint32_t)(wncol + p * 16) * LDR + ko + b_off);
                bl[2 * p][0] = r[0]; bl[2 * p][1] = r[1];
                bl[2 * p + 1][0] = r[2]; bl[2 * p + 1][1] = r[3];
            }
            #pragma unroll
            for (int mt = 0; mt < 4; mt++)
                #pragma unroll
                for (int nt = 0; nt < 8; nt++) mma_bf16(acc[mt][nt], af[mt], bl[nt]);
            #pragma unroll
            for (int mt = 0; mt < 4; mt++)
                ldsm4(af[mt], sAl + (uint32_t)(wm * 64 + mt * 16) * LDR + ko + a_off);
            #pragma unroll
            for (int mt = 0; mt < 4; mt++)
                #pragma unroll
                for (int nt = 0; nt < 8; nt++) mma_bf16(acc[mt][nt], af[mt], bh[nt]);
        }
        __syncthreads();
    }

    #pragma unroll
    for (int mt = 0; mt < 4; mt++) {
        #pragma unroll
        for (int h = 0; h < 2; h++) {
            const int row = m0 + wm * 64 + mt * 16 + (lane >> 2) + h * 8;
            #pragma unroll
            for (int nt = 0; nt < 8; nt++) {
                const int col = n0 + wncol + nt * 8 + (lane & 3) * 2;
                float v0 = acc[mt][nt][h * 2 + 0];
                float v1 = acc[mt][nt][h * 2 + 1];
                if (flags & F_BCOL) { v0 += bias[col]; v1 += bias[col + 1]; }
                const size_t idx = (size_t)row * ldc + col;
                if (flags & F_SPLIT) {
                    __nv_bfloat16 h0 = __float2bfloat16_rn(v0);
                    __nv_bfloat16 h1 = __float2bfloat16_rn(v1);
                    __nv_bfloat16 l0 = __float2bfloat16_rn(v0 - __bfloat162float(h0));
                    __nv_bfloat16 l1 = __float2bfloat16_rn(v1 - __bfloat162float(h1));
                    uint32_t hp = (uint32_t)__bfloat16_as_ushort(h0) | ((uint32_t)__bfloat16_as_ushort(h1) << 16);
                    uint32_t lp = (uint32_t)__bfloat16_as_ushort(l0) | ((uint32_t)__bfloat16_as_ushort(l1) << 16);
                    *(uint32_t*)(Chi + (size_t)bz * sC + idx) = hp;
                    *(uint32_t*)(Clo + (size_t)bz * sC + idx) = lp;
                } else {
                    float2 o;
                    o.x = v0;
                    o.y = v1;
                    *(float2*)(Cf + (size_t)bz * sC + idx) = o;
                }
            }
        }
    }
}

// ---------------------------------------------------------------------------
// 1-pass f16 GEMM, f16 accumulators + windowed f32 flush (every 8 chunks).
// CTA 128x128, warp 64x32 (2x4 warps), K-chunk 32, double buffer.
// ---------------------------------------------------------------------------
#define A1_TILE  (128 * LDR)       // 10240
#define H1_STAGE (2 * A1_TILE)     // 20480
#define H1_SMEM  (2 * H1_STAGE)    // 40960

__global__ void __launch_bounds__(256, 1)
tgemm_h1(const __half* __restrict__ A, const __half* __restrict__ Bs,
         float* __restrict__ Cf, __half* __restrict__ Ch,
         const float* __restrict__ bias, const float* __restrict__ R,
         const float* __restrict__ gammap,
         int Kd, int ldc, size_t sA, size_t sB, size_t sC, size_t sR, int flags)
{
    extern __shared__ char smem[];
    const uint32_t sm0 = smem_to_u32(smem);
    const int tid = threadIdx.x, wid = tid >> 5, lane = tid & 31;
    const int bz = blockIdx.z;
    const int m0 = blockIdx.y * 128;
    const int n0 = blockIdx.x * 128;

    const size_t ldkB = (size_t)Kd * 2;
    const int lt = tid >> 7;               // 0 = A tile, 1 = B tile
    const int r0 = (tid >> 2) & 31;        // row base (stride 32)
    const int seg = tid & 3;
    const char* gthr = (lt ? (const char*)(Bs + (size_t)bz * sB) + (size_t)(n0 + r0) * ldkB
                           : (const char*)(A  + (size_t)bz * sA) + (size_t)(m0 + r0) * ldkB)
                       + seg * 16;
    const size_t g32 = 32 * ldkB;
    const uint32_t dthr = sm0 + (uint32_t)lt * A1_TILE + (uint32_t)r0 * LDR + (uint32_t)seg * 16;

    const int nch = Kd >> 5;
    const int wm = wid & 1;
    const int wncol = (wid >> 1) * 32;
    const uint32_t a_off = (uint32_t)((lane & 15) * LDR + (lane >> 4) * 16);
    const uint32_t b_off = (uint32_t)(((lane & 7) + ((lane >> 4) & 1) * 8) * LDR + ((lane >> 3) & 1) * 16);

    float acc[4][4][4];
    uint32_t hacc[4][4][2];
    #pragma unroll
    for (int i = 0; i < 4; i++)
        #pragma unroll
        for (int j = 0; j < 4; j++) {
            hacc[i][j][0] = 0u; hacc[i][j][1] = 0u;
            #pragma unroll
            for (int k = 0; k < 4; k++) acc[i][j][k] = 0.f;
        }

#define H1_LOAD(s, c) do { \
        const size_t _ko = (size_t)(c) * 64; \
        const uint32_t _d = dthr + (uint32_t)(s) * H1_STAGE; \
        _Pragma("unroll") \
        for (int _j = 0; _j < 4; _j++) \
            cp16(_d + _j * 32 * LDR, gthr + _ko + _j * g32); \
        cp_commit(); \
    } while (0)

    H1_LOAD(0, 0);

    for (int c = 0; c < nch; c++) {
        const int s = c & 1;
        if (c + 1 < nch) { H1_LOAD(s ^ 1, c + 1); cp_wait1(); }
        else             { cp_wait0(); }
        __syncthreads();

        const uint32_t sb = sm0 + (uint32_t)s * H1_STAGE;
        const uint32_t sA_ = sb, sB_ = sb + A1_TILE;

        #pragma unroll
        for (int ks = 0; ks < 2; ks++) {
            const uint32_t ko = ks * 32;
            uint32_t bf[4][2], af[4][4];
            #pragma unroll
            for (int p = 0; p < 2; p++) {
                uint32_t r[4];
                ldsm4(r, sB_ + (uint32_t)(wncol + p * 16) * LDR + ko + b_off);
                bf[2 * p][0] = r[0]; bf[2 * p][1] = r[1];
                bf[2 * p + 1][0] = r[2]; bf[2 * p + 1][1] = r[3];
            }
            #pragma unroll
            for (int mt = 0; mt < 4; mt++)
                ldsm4(af[mt], sA_ + (uint32_t)(wm * 64 + mt * 16) * LDR + ko + a_off);
            #pragma unroll
            for (int mt = 0; mt < 4; mt++)
                #pragma unroll
                for (int nt = 0; nt < 4; nt++) mma_f16acc(hacc[mt][nt], af[mt], bf[nt]);
        }

        if ((c & 7) == 7 || c == nch - 1) {
            #pragma unroll
            for (int mt = 0; mt < 4; mt++)
                #pragma unroll
                for (int nt = 0; nt < 4; nt++) {
                    float2 f0 = __half22float2(*(__half2*)&hacc[mt][nt][0]);
                    float2 f1 = __half22float2(*(__half2*)&hacc[mt][nt][1]);
                    acc[mt][nt][0] += f0.x; acc[mt][nt][1] += f0.y;
                    acc[mt][nt][2] += f1.x; acc[mt][nt][3] += f1.y;
                    hacc[mt][nt][0] = 0u; hacc[mt][nt][1] = 0u;
                }
        }
        __syncthreads();
    }

    if (flags & F_RES) {
        const float g = *gammap;
        #pragma unroll
        for (int mt = 0; mt < 4; mt++)
            #pragma unroll
            for (int h = 0; h < 2; h++) {
                const int row = m0 + wm * 64 + mt * 16 + (lane >> 2) + h * 8;
                #pragma unroll
                for (int nt = 0; nt < 4; nt++) {
                    const int col = n0 + wncol + nt * 8 + (lane & 3) * 2;
                    const size_t idx = (size_t)row * ldc + col;
                    const float2 rv = *(const float2*)(R + (size_t)bz * sR + idx);
                    float2 o;
                    o.x = g * acc[mt][nt][h * 2 + 0] + rv.x;
                    o.y = g * acc[mt][nt][h * 2 + 1] + rv.y;
                    *(float2*)(Cf + (size_t)bz * sC + idx) = o;
                }
            }
    } else {
        #pragma unroll
        for (int mt = 0; mt < 4; mt++)
            #pragma unroll
            for (int h = 0; h < 2; h++) {
                const int row = m0 + wm * 64 + mt * 16 + (lane >> 2) + h * 8;
                const float br = bias[row];
                #pragma unroll
                for (int nt = 0; nt < 4; nt++) {
                    const int col = n0 + wncol + nt * 8 + (lane & 3) * 2;
                    const size_t idx = (size_t)row * ldc + col;
                    __half2 p2 = __floats2half2_rn(acc[mt][nt][h * 2 + 0] + br,
                                                   acc[mt][nt][h * 2 + 1] + br);
                    *(uint32_t*)(Ch + (size_t)bz * sC + idx) = *(uint32_t*)&p2;
                }
            }
    }
}

// ---------------------------------------------------------------------------
__global__ void prep_split(const float* __restrict__ Wq, const float* __restrict__ Wk,
                           const float* __restrict__ Wv,
                           __nv_bfloat16* __restrict__ Wq_h, __nv_bfloat16* __restrict__ Wq_l,
                           __nv_bfloat16* __restrict__ Wk_h, __nv_bfloat16* __restrict__ Wk_l,
                           __half* __restrict__ Wv_f)
{
    const int i = blockIdx.x * blockDim.x + threadIdx.x;
    const int nqk = 256 * 512;
    if (i < 2 * nqk) {
        const float* src = (i < nqk) ? Wq : Wk;
        __nv_bfloat16* H = (i < nqk) ? Wq_h : Wk_h;
        __nv_bfloat16* L = (i < nqk) ? Wq_l : Wk_l;
        const int j = (i < nqk) ? i : i - nqk;
        const float v = src[j];
        const __nv_bfloat16 h = __float2bfloat16_rn(v);
        H[j] = h;
        L[j] = __float2bfloat16_rn(v - __bfloat162float(h));
    } else if (i < 2 * nqk + 512 * 512) {
        const int j = i - 2 * nqk;
        Wv_f[j] = __float2half_rn(Wv[j]);
    }
}

__global__ __launch_bounds__(256)
void transpose_all(const float* __restrict__ Q, const float* __restrict__ Kin,
                   const float* __restrict__ V,
                   __nv_bfloat16* __restrict__ Qh, __nv_bfloat16* __restrict__ Ql,
                   __nv_bfloat16* __restrict__ Kh, __nv_bfloat16* __restrict__ Kl,
                   __half* __restrict__ Vt,
                   int rows, int cols, int batch)
{
    __shared__ float t[32][33];
    const int z = blockIdx.z;
    const int tsel = z / batch, bz = z % batch;
    const float* X = (tsel == 0) ? Q : (tsel == 1) ? Kin : V;
    const size_t bo = (size_t)bz * rows * cols;
    X += bo;
    const int x0 = blockIdx.x * 32;
    const int y0 = blockIdx.y * 32;
    const int tx = threadIdx.x & 31, ty = threadIdx.x >> 5;

    #pragma unroll
    for (int j = 0; j < 32; j += 8)
        t[ty + j][tx] = X[(size_t)(y0 + ty + j) * cols + x0 + tx];
    __syncthreads();

    if (tsel < 2) {
        __nv_bfloat16* Th = ((tsel == 0) ? Qh : Kh) + bo;
        __nv_bfloat16* Tl = ((tsel == 0) ? Ql : Kl) + bo;
        #pragma unroll
        for (int j = 0; j < 32; j += 8) {
            const float v = t[tx][ty + j];
            const __nv_bfloat16 h = __float2bfloat16_rn(v);
            const __nv_bfloat16 l = __float2bfloat16_rn(v - __bfloat162float(h));
            const size_t idx = (size_t)(x0 + ty + j) * rows + y0 + tx;
            Th[idx] = h;
            Tl[idx] = l;
        }
    } else {
        __half* Tv = Vt + bo;
        #pragma unroll
        for (int j = 0; j < 32; j += 8) {
            const size_t idx = (size_t)(x0 + ty + j) * rows + y0 + tx;
            Tv[idx] = __float2half_rn(t[tx][ty + j]);
        }
    }
}

__device__ __forceinline__ float fexp(float x) {
    float t = fmaxf(x * 1.44269504f, -126.f);
    float fi = floorf(t);
    float f = t - fi;
    float p = 1.5465324e-4f;
    p = p * f + 1.3333558e-3f;
    p = p * f + 9.6181291e-3f;
    p = p * f + 5.5504109e-2f;
    p = p * f + 2.4022651e-1f;
    p = p * f + 6.9314718e-1f;
    p = p * f + 1.0f;
    return p * __int_as_float(((int)fi + 127) << 23);
}

__global__ __launch_bounds__(256)
void softmax_row(const float* __restrict__ E, __half* __restrict__ A, int Ncols)
{
    const int row = blockIdx.x;
    const int bz = blockIdx.y;
    const size_t base = ((size_t)bz * gridDim.x + row) * Ncols;
    const int tid = threadIdx.x, wid = tid >> 5, lid = tid & 31;

    __shared__ float sbuf[8];

    float x[16];
    const float4* rp = (const float4*)(E + base);
    #pragma unroll
    for (int k = 0; k < 4; k++) {
        float4 v4 = rp[tid + k * 256];
        x[k * 4 + 0] = v4.x; x[k * 4 + 1] = v4.y; x[k * 4 + 2] = v4.z; x[k * 4 + 3] = v4.w;
    }

    float m = x[0];
    #pragma unroll
    for (int i = 1; i < 16; i++) m = fmaxf(m, x[i]);
    #pragma unroll
    for (int o = 16; o; o >>= 1) m = fmaxf(m, __shfl_xor_sync(0xffffffffu, m, o));
    if (lid == 0) sbuf[wid] = m;
    __syncthreads();
    float mx = sbuf[0];
    #pragma unroll
    for (int i = 1; i < 8; i++) mx = fmaxf(mx, sbuf[i]);
    __syncthreads();

    float s = 0.f;
    #pragma unroll
    for (int i = 0; i < 16; i++) { x[i] = fexp(x[i] - mx); s += x[i]; }
    #pragma unroll
    for (int o = 16; o; o >>= 1) s += __shfl_xor_sync(0xffffffffu, s, o);
    if (lid == 0) sbuf[wid] = s;
    __syncthreads();
    float tot = 0.f;
    #pragma unroll
    for (int i = 0; i < 8; i++) tot += sbuf[i];
    const float inv = 1.f / tot;

    #pragma unroll
    for (int k = 0; k < 4; k++) {
        uint32_t hp[2];
        #pragma unroll
        for (int j = 0; j < 2; j++) {
            __half2 p2 = __floats2half2_rn(x[k * 4 + 2 * j] * inv, x[k * 4 + 2 * j + 1] * inv);
            hp[j] = *(uint32_t*)&p2;
        }
        const size_t idx = base + (size_t)(tid + k * 256) * 4;
        *(uint2*)(A + idx) = *(const uint2*)hp;
    }
}

// ---------------------------------------------------------------------------
extern "C" void kernel_launch(void* const* d_in, const int* in_sizes, int n_in,
                              void* d_out, int out_size)
{
    const float* Q     = (const float*)d_in[0];
    const float* Kin   = (const float*)d_in[1];
    const float* V     = (const float*)d_in[2];
    const float* Wq    = (const float*)d_in[3];
    const float* bq    = (const float*)d_in[4];
    const float* Wk    = (const float*)d_in[5];
    const float* bk    = (const float*)d_in[6];
    const float* Wv    = (const float*)d_in[7];
    const float* bv    = (const float*)d_in[8];
    const float* gamma = (const float*)d_in[9];
    float* out = (float*)d_out;

    __nv_bfloat16 *Qt_h, *Qt_l, *Kt_h, *Kt_l;
    __half *Vt, *Wv_f, *v, *a;
    __nv_bfloat16 *Wq_h, *Wq_l, *Wk_h, *Wk_l;
    __nv_bfloat16 *qt_h, *qt_l, *kt_h, *kt_l;
    float* e;
    cudaGetSymbolAddress((void**)&Qt_h, g_Qt_h); cudaGetSymbolAddress((void**)&Qt_l, g_Qt_l);
    cudaGetSymbolAddress((void**)&Kt_h, g_Kt_h); cudaGetSymbolAddress((void**)&Kt_l, g_Kt_l);
    cudaGetSymbolAddress((void**)&Vt,   g_Vt);
    cudaGetSymbolAddress((void**)&Wq_h, g_Wq_h); cudaGetSymbolAddress((void**)&Wq_l, g_Wq_l);
    cudaGetSymbolAddress((void**)&Wk_h, g_Wk_h); cudaGetSymbolAddress((void**)&Wk_l, g_Wk_l);
    cudaGetSymbolAddress((void**)&Wv_f, g_Wv);
    cudaGetSymbolAddress((void**)&qt_h, g_qt_h); cudaGetSymbolAddress((void**)&qt_l, g_qt_l);
    cudaGetSymbolAddress((void**)&kt_h, g_kt_h); cudaGetSymbolAddress((void**)&kt_l, g_kt_l);
    cudaGetSymbolAddress((void**)&v,    g_v);
    cudaGetSymbolAddress((void**)&a,    g_a);
    cudaGetSymbolAddress((void**)&e,    g_e);

    const int B = B_, C = C_, CH = CH_, N = N_;

    cudaFuncSetAttribute(tgemm_kernel, cudaFuncAttributeMaxDynamicSharedMemorySize, TG_SMEM);
    cudaFuncSetAttribute(tgemm_h1, cudaFuncAttributeMaxDynamicSharedMemorySize, H1_SMEM);

    // 0: weight prep (Wq/Wk bf16 hi/lo, Wv f16)
    const int nsplit = 2 * CH * C + C * C;
    prep_split<<<(nsplit + 255) / 256, 256>>>(Wq, Wk, Wv, Wq_h, Wq_l, Wk_h, Wk_l, Wv_f);

    // 1: input transpose (Q,K bf16 hi/lo; V f16)
    transpose_all<<<dim3(N / 32, C / 32, 3 * B), 256>>>(
        Q, Kin, V, Qt_h, Qt_l, Kt_h, Kt_l, Vt, C, N, B);

    // 2: qt[n][ch] = Qt . Wq^T + bq[ch]
    tgemm_kernel<<<dim3(CH / 256, N / 128, B), 256, TG_SMEM>>>(
        Qt_h, Qt_l, Wq_h, Wq_l, nullptr, qt_h, qt_l, bq,
        C, CH, (size_t)N * C, 0, (size_t)N * CH, F_SPLIT | F_BCOL);
    // 3: kt
    tgemm_kernel<<<dim3(CH / 256, N / 128, B), 256, TG_SMEM>>>(
        Kt_h, Kt_l, Wk_h, Wk_l, nullptr, kt_h, kt_l, bk,
        C, CH, (size_t)N * C, 0, (size_t)N * CH, F_SPLIT | F_BCOL);

    // 4: v[c][n] = Wv . Vt^T + bv[c]   (1-pass f16, f16-accum windowed)
    tgemm_h1<<<dim3(N / 128, C / 128, B), 256, H1_SMEM>>>(
        Wv_f, Vt, nullptr, v, bv, nullptr, nullptr,
        C, N, 0, (size_t)N * C, (size_t)C * N, 0, F_BROW);

    // 5 (profiled): e[n][m] = qt . kt^T   (bf16 split-3, f32 out)
    tgemm_kernel<<<dim3(N / 256, N / 128, B), 256, TG_SMEM>>>(
        qt_h, qt_l, kt_h, kt_l, e, nullptr, nullptr, nullptr,
        CH, N, (size_t)N * CH, (size_t)N * CH, (size_t)N * N, 0);

    // 6: attention = softmax_m(e) -> single f16
    softmax_row<<<dim3(N, B), 256>>>(e, a, N);

    // 7: out[c][n] = gamma * (v . attn^T) + V   (1-pass f16, f16-accum windowed)
    tgemm_h1<<<dim3(N / 128, C / 128, B), 256, H1_SMEM>>>(
        v, a, out, nullptr, nullptr, V, gamma,
        N, N, (size_t)C * N, (size_t)N * N, (size_t)C * N, (size_t)C * N, F_RES);
}

// round 14
// speedup vs baseline: 1.1084x; 1.1084x over previous
#include <cuda_runtime.h>
#include <cuda_bf16.h>
#include <cuda_fp16.h>
#include <cstdint>

// ---------------------------------------------------------------------------
// AttentionModule via mma.sync m16n8k16 (legacy HMMA; tcgen05 ptxas-gated off;
// measured HW cap ~585 MACs/cyc/SM, f16-accum confirmed NOT faster (r11)).
// Pass-minimal schedule:
//   q/k projections: bf16 split-3 (logits amplify errors x16 -> need 2^-16)
//   v projection:    1-pass f16 (Wv single f16 x Vt f16), f32 accum
//   energy:          bf16 split-3, f32 out
//   softmax:         poly-exp, row in regs, attention stored single f16
//   out:             1-pass f16 (v x attn), f32 accum, epilogue gamma*acc + V
// ---------------------------------------------------------------------------

static const int B_ = 4, C_ = 512, CH_ = 256, N_ = 4096;

// ---------------- scratch ----------------
__device__ __align__(256) __nv_bfloat16 g_Qt_h[4L * 4096 * 512];
__device__ __align__(256) __nv_bfloat16 g_Qt_l[4L * 4096 * 512];
__device__ __align__(256) __nv_bfloat16 g_Kt_h[4L * 4096 * 512];
__device__ __align__(256) __nv_bfloat16 g_Kt_l[4L * 4096 * 512];
__device__ __align__(256) __half        g_Vt  [4L * 4096 * 512];
__device__ __align__(256) __nv_bfloat16 g_Wq_h[256 * 512];
__device__ __align__(256) __nv_bfloat16 g_Wq_l[256 * 512];
__device__ __align__(256) __nv_bfloat16 g_Wk_h[256 * 512];
__device__ __align__(256) __nv_bfloat16 g_Wk_l[256 * 512];
__device__ __align__(256) __half        g_Wv  [512 * 512];
__device__ __align__(256) __nv_bfloat16 g_qt_h[4L * 4096 * 256];
__device__ __align__(256) __nv_bfloat16 g_qt_l[4L * 4096 * 256];
__device__ __align__(256) __nv_bfloat16 g_kt_h[4L * 4096 * 256];
__device__ __align__(256) __nv_bfloat16 g_kt_l[4L * 4096 * 256];
__device__ __align__(256) __half        g_v   [4L * 512 * 4096];
__device__ __align__(256) float         g_e   [4L * 4096 * 4096];
__device__ __align__(256) __half        g_a   [4L * 4096 * 4096];

// ---------------- helpers ----------------
__device__ __forceinline__ uint32_t smem_to_u32(const void* p) {
    uint32_t a;
    asm("{ .reg .u64 t; cvta.to.shared.u64 t, %1; cvt.u32.u64 %0, t; }" : "=r"(a) : "l"(p));
    return a;
}
__device__ __forceinline__ void cp16(uint32_t dst, const void* src) {
    asm volatile("cp.async.cg.shared.global [%0], [%1], 16;" :: "r"(dst), "l"(src) : "memory");
}
__device__ __forceinline__ void cp_commit() { asm volatile("cp.async.commit_group;" ::: "memory"); }
__device__ __forceinline__ void cp_wait1()  { asm volatile("cp.async.wait_group 1;" ::: "memory"); }
__device__ __forceinline__ void cp_wait0()  { asm volatile("cp.async.wait_group 0;" ::: "memory"); }

__device__ __forceinline__ void ldsm4(uint32_t* r, uint32_t a) {
    asm volatile("ldmatrix.sync.aligned.m8n8.x4.shared.b16 {%0,%1,%2,%3}, [%4];"
                 : "=r"(r[0]), "=r"(r[1]), "=r"(r[2]), "=r"(r[3]) : "r"(a));
}
__device__ __forceinline__ void mma_bf16(float* c, const uint32_t* a, const uint32_t* b) {
    asm volatile("mma.sync.aligned.m16n8k16.row.col.f32.bf16.bf16.f32 "
                 "{%0,%1,%2,%3}, {%4,%5,%6,%7}, {%8,%9}, {%0,%1,%2,%3};"
                 : "+f"(c[0]), "+f"(c[1]), "+f"(c[2]), "+f"(c[3])
                 : "r"(a[0]), "r"(a[1]), "r"(a[2]), "r"(a[3]), "r"(b[0]), "r"(b[1]));
}
__device__ __forceinline__ void mma_f16(float* c, const uint32_t* a, const uint32_t* b) {
    asm volatile("mma.sync.aligned.m16n8k16.row.col.f32.f16.f16.f32 "
                 "{%0,%1,%2,%3}, {%4,%5,%6,%7}, {%8,%9}, {%0,%1,%2,%3};"
                 : "+f"(c[0]), "+f"(c[1]), "+f"(c[2]), "+f"(c[3])
                 : "r"(a[0]), "r"(a[1]), "r"(a[2]), "r"(a[3]), "r"(b[0]), "r"(b[1]));
}

#define LDR     80
#define A_TILE  (128 * LDR)
#define B_TILE  (256 * LDR)

enum { F_SPLIT = 1, F_BROW = 2, F_BCOL = 4, F_RES = 8 };

// ---------------------------------------------------------------------------
// bf16 split-3 tgemm (q/k projections + energy). CTA 128x256, warp 64x64.
// ---------------------------------------------------------------------------
#define STAGE_S (2 * A_TILE + 2 * B_TILE)   // 61440
#define TG_SMEM (2 * STAGE_S)               // 122880

__global__ void __launch_bounds__(256, 1)
tgemm_kernel(const __nv_bfloat16* __restrict__ Ah, const __nv_bfloat16* __restrict__ Al,
             const __nv_bfloat16* __restrict__ Bh, const __nv_bfloat16* __restrict__ Bl,
             float* __restrict__ Cf, __nv_bfloat16* __restrict__ Chi, __nv_bfloat16* __restrict__ Clo,
             const float* __restrict__ bias,
             int Kd, int ldc, size_t sA, size_t sB, size_t sC, int flags)
{
    extern __shared__ char smem[];
    const uint32_t sm0 = smem_to_u32(smem);
    const int tid = threadIdx.x, wid = tid >> 5, lane = tid & 31;
    const int bz = blockIdx.z;
    const int m0 = blockIdx.y * 128;
    const int n0 = blockIdx.x * 256;

    const size_t ldkB = (size_t)Kd * 2;
    const int lr = tid >> 2, seg = tid & 3;
    const char* gA_h = (const char*)(Ah + (size_t)bz * sA) + (size_t)(m0 + lr) * ldkB + seg * 16;
    const char* gA_l = (const char*)(Al + (size_t)bz * sA) + (size_t)(m0 + lr) * ldkB + seg * 16;
    const char* gB_h = (const char*)(Bh + (size_t)bz * sB) + (size_t)(n0 + lr) * ldkB + seg * 16;
    const char* gB_l = (const char*)(Bl + (size_t)bz * sB) + (size_t)(n0 + lr) * ldkB + seg * 16;
    const size_t g64 = 64 * ldkB;
    const uint32_t dthr = sm0 + (uint32_t)lr * LDR + (uint32_t)seg * 16;

    const int nch = Kd >> 5;
    const int wm = wid & 1;
    const int wncol = (wid >> 1) * 64;
    const uint32_t a_off = (uint32_t)((lane & 15) * LDR + (lane >> 4) * 16);
    const uint32_t b_off = (uint32_t)(((lane & 7) + ((lane >> 4) & 1) * 8) * LDR + ((lane >> 3) & 1) * 16);

    float acc[4][8][4];
    #pragma unroll
    for (int i = 0; i < 4; i++)
        #pragma unroll
        for (int j = 0; j < 8; j++)
            #pragma unroll
            for (int k = 0; k < 4; k++) acc[i][j][k] = 0.f;

#define TG_LOAD(s, c) do { \
        const size_t _ko = (size_t)(c) * 64; \
        const uint32_t _d = dthr + (uint32_t)(s) * STAGE_S; \
        cp16(_d,                     gA_h + _ko); \
        cp16(_d + 64 * LDR,          gA_h + _ko + g64); \
        cp16(_d + A_TILE,            gA_l + _ko); \
        cp16(_d + A_TILE + 64 * LDR, gA_l + _ko + g64); \
        _Pragma("unroll") \
        for (int _j = 0; _j < 4; _j++) \
            cp16(_d + 2 * A_TILE + _j * 64 * LDR, gB_h + _ko + _j * g64); \
        _Pragma("unroll") \
        for (int _j = 0; _j < 4; _j++) \
            cp16(_d + 2 * A_TILE + B_TILE + _j * 64 * LDR, gB_l + _ko + _j * g64); \
        cp_commit(); \
    } while (0)

    TG_LOAD(0, 0);

    for (int c = 0; c < nch; c++) {
        const int s = c & 1;
        if (c + 1 < nch) { TG_LOAD(s ^ 1, c + 1); cp_wait1(); }
        else             { cp_wait0(); }
        __syncthreads();

        const uint32_t sb  = sm0 + (uint32_t)s * STAGE_S;
        const uint32_t sAh = sb, sAl = sb + A_TILE;
        const uint32_t sBh = sb + 2 * A_TILE, sBl = sBh + B_TILE;

        #pragma unroll
        for (int ks = 0; ks < 2; ks++) {
            const uint32_t ko = ks * 32;
            uint32_t bh[8][2], bl[8][2], af[4][4];
            #pragma unroll
            for (int p = 0; p < 4; p++) {
                uint32_t r[4];
                ldsm4(r, sBh + (uint32_t)(wncol + p * 16) * LDR + ko + b_off);
                bh[2 * p][0] = r[0]; bh[2 * p][1] = r[1];
                bh[2 * p + 1][0] = r[2]; bh[2 * p + 1][1] = r[3];
            }
            #pragma unroll
            for (int mt = 0; mt < 4; mt++)
                ldsm4(af[mt], sAh + (uint32_t)(wm * 64 + mt * 16) * LDR + ko + a_off);
            #pragma unroll
            for (int mt = 0; mt < 4; mt++)
                #pragma unroll
                for (int nt = 0; nt < 8; nt++) mma_bf16(acc[mt][nt], af[mt], bh[nt]);
            #pragma unroll
            for (int p = 0; p < 4; p++) {
                uint32_t r[4];
                ldsm4(r, sBl + (uint32_t)(wncol + p * 16) * LDR + ko + b_off);
                bl[2 * p][0] = r[0]; bl[2 * p][1] = r[1];
                bl[2 * p + 1][0] = r[2]; bl[2 * p + 1][1] = r[3];
            }
            #pragma unroll
            for (int mt = 0; mt < 4; mt++)
                #pragma unroll
                for (int nt = 0; nt < 8; nt++) mma_bf16(acc[mt][nt], af[mt], bl[nt]);
            #pragma unroll
            for (int mt = 0; mt < 4; mt++)
                ldsm4(af[mt], sAl + (uint32_t)(wm * 64 + mt * 16) * LDR + ko + a_off);
            #pragma unroll
            for (int mt = 0; mt < 4; mt++)
                #pragma unroll
                for (int nt = 0; nt < 8; nt++) mma_bf16(acc[mt][nt], af[mt], bh[nt]);
        }
        __syncthreads();
    }

    // epilogue
    #pragma unroll
    for (int mt = 0; mt < 4; mt++) {
        #pragma unroll
        for (int h = 0; h < 2; h++) {
            const int row = m0 + wm * 64 + mt * 16 + (lane >> 2) + h * 8;
            #pragma unroll
            for (int nt = 0; nt < 8; nt++) {
                const int col = n0 + wncol + nt * 8 + (lane & 3) * 2;
                float v0 = acc[mt][nt][h * 2 + 0];
                float v1 = acc[mt][nt][h * 2 + 1];
                if (flags & F_BCOL) { v0 += bias[col]; v1 += bias[col + 1]; }
                const size_t idx = (size_t)row * ldc + col;
                if (flags & F_SPLIT) {
                    __nv_bfloat16 h0 = __float2bfloat16_rn(v0);
                    __nv_bfloat16 h1 = __float2bfloat16_rn(v1);
                    __nv_bfloat16 l0 = __float2bfloat16_rn(v0 - __bfloat162float(h0));
                    __nv_bfloat16 l1 = __float2bfloat16_rn(v1 - __bfloat162float(h1));
                    uint32_t hp = (uint32_t)__bfloat16_as_ushort(h0) | ((uint32_t)__bfloat16_as_ushort(h1) << 16);
                    uint32_t lp = (uint32_t)__bfloat16_as_ushort(l0) | ((uint32_t)__bfloat16_as_ushort(l1) << 16);
                    *(uint32_t*)(Chi + (size_t)bz * sC + idx) = hp;
                    *(uint32_t*)(Clo + (size_t)bz * sC + idx) = lp;
                } else {
                    float2 o;
                    o.x = v0;
                    o.y = v1;
                    *(float2*)(Cf + (size_t)bz * sC + idx) = o;
                }
            }
        }
    }
}

// ---------------------------------------------------------------------------
// f16 GEMM, TWO=1: D = (Ah+Al).B^T (2 passes); TWO=0: D = Ah.B^T (1 pass).
// f32 accumulators. CTA 128x256, warp 64x64.
// Epilogue: F_RES -> f32 gamma*acc + R  else f16 single with row bias.
// ---------------------------------------------------------------------------
template <int TWO>
__global__ void __launch_bounds__(256, 1)
tgemm_h(const __half* __restrict__ Ah, const __half* __restrict__ Al,
        const __half* __restrict__ Bs,
        float* __restrict__ Cf, __half* __restrict__ Ch,
        const float* __restrict__ bias, const float* __restrict__ R,
        const float* __restrict__ gammap,
        int Kd, int ldc, size_t sA, size_t sB, size_t sC, size_t sR, int flags)
{
    constexpr int H_STAGE = (TWO ? 2 : 1) * A_TILE + B_TILE;
    extern __shared__ char smem[];
    const uint32_t sm0 = smem_to_u32(smem);
    const int tid = threadIdx.x, wid = tid >> 5, lane = tid & 31;
    const int bz = blockIdx.z;
    const int m0 = blockIdx.y * 128;
    const int n0 = blockIdx.x * 256;

    const size_t ldkB = (size_t)Kd * 2;
    const int lr = tid >> 2, seg = tid & 3;
    const char* gA_h = (const char*)(Ah + (size_t)bz * sA) + (size_t)(m0 + lr) * ldkB + seg * 16;
    const char* gA_l = TWO ? (const char*)(Al + (size_t)bz * sA) + (size_t)(m0 + lr) * ldkB + seg * 16 : nullptr;
    const char* gB   = (const char*)(Bs + (size_t)bz * sB) + (size_t)(n0 + lr) * ldkB + seg * 16;
    const size_t g64 = 64 * ldkB;
    const uint32_t dthr = sm0 + (uint32_t)lr * LDR + (uint32_t)seg * 16;
    const uint32_t boff_b = (TWO ? 2 : 1) * A_TILE;

    const int nch = Kd >> 5;
    const int wm = wid & 1;
    const int wncol = (wid >> 1) * 64;
    const uint32_t a_off = (uint32_t)((lane & 15) * LDR + (lane >> 4) * 16);
    const uint32_t b_off = (uint32_t)(((lane & 7) + ((lane >> 4) & 1) * 8) * LDR + ((lane >> 3) & 1) * 16);

    float acc[4][8][4];
    #pragma unroll
    for (int i = 0; i < 4; i++)
        #pragma unroll
        for (int j = 0; j < 8; j++)
            #pragma unroll
            for (int k = 0; k < 4; k++) acc[i][j][k] = 0.f;

#define TH_LOAD(s, c) do { \
        const size_t _ko = (size_t)(c) * 64; \
        const uint32_t _d = dthr + (uint32_t)(s) * H_STAGE; \
        cp16(_d,            gA_h + _ko); \
        cp16(_d + 64 * LDR, gA_h + _ko + g64); \
        if (TWO) { \
            cp16(_d + A_TILE,            gA_l + _ko); \
            cp16(_d + A_TILE + 64 * LDR, gA_l + _ko + g64); \
        } \
        _Pragma("unroll") \
        for (int _j = 0; _j < 4; _j++) \
            cp16(_d + boff_b + _j * 64 * LDR, gB + _ko + _j * g64); \
        cp_commit(); \
    } while (0)

    TH_LOAD(0, 0);

    for (int c = 0; c < nch; c++) {
        const int s = c & 1;
        if (c + 1 < nch) { TH_LOAD(s ^ 1, c + 1); cp_wait1(); }
        else             { cp_wait0(); }
        __syncthreads();

        const uint32_t sb  = sm0 + (uint32_t)s * H_STAGE;
        const uint32_t sAh = sb, sAl = sb + A_TILE, sB_ = sb + boff_b;

        #pragma unroll
        for (int ks = 0; ks < 2; ks++) {
            const uint32_t ko = ks * 32;
            uint32_t bf[8][2], af[4][4];
            #pragma unroll
            for (int p = 0; p < 4; p++) {
                uint32_t r[4];
                ldsm4(r, sB_ + (uint32_t)(wncol + p * 16) * LDR + ko + b_off);
                bf[2 * p][0] = r[0]; bf[2 * p][1] = r[1];
                bf[2 * p + 1][0] = r[2]; bf[2 * p + 1][1] = r[3];
            }
            #pragma unroll
            for (int mt = 0; mt < 4; mt++)
                ldsm4(af[mt], sAh + (uint32_t)(wm * 64 + mt * 16) * LDR + ko + a_off);
            #pragma unroll
            for (int mt = 0; mt < 4; mt++)
                #pragma unroll
                for (int nt = 0; nt < 8; nt++) mma_f16(acc[mt][nt], af[mt], bf[nt]);
            if (TWO) {
                #pragma unroll
                for (int mt = 0; mt < 4; mt++)
                    ldsm4(af[mt], sAl + (uint32_t)(wm * 64 + mt * 16) * LDR + ko + a_off);
                #pragma unroll
                for (int mt = 0; mt < 4; mt++)
                    #pragma unroll
                    for (int nt = 0; nt < 8; nt++) mma_f16(acc[mt][nt], af[mt], bf[nt]);
            }
        }
        __syncthreads();
    }

    if (flags & F_RES) {
        const float g = *gammap;
        #pragma unroll
        for (int mt = 0; mt < 4; mt++)
            #pragma unroll
            for (int h = 0; h < 2; h++) {
                const int row = m0 + wm * 64 + mt * 16 + (lane >> 2) + h * 8;
                #pragma unroll
                for (int nt = 0; nt < 8; nt++) {
                    const int col = n0 + wncol + nt * 8 + (lane & 3) * 2;
                    const size_t idx = (size_t)row * ldc + col;
                    const float2 rv = *(const float2*)(R + (size_t)bz * sR + idx);
                    float2 o;
                    o.x = g * acc[mt][nt][h * 2 + 0] + rv.x;
                    o.y = g * acc[mt][nt][h * 2 + 1] + rv.y;
                    *(float2*)(Cf + (size_t)bz * sC + idx) = o;
                }
            }
    } else {
        #pragma unroll
        for (int mt = 0; mt < 4; mt++)
            #pragma unroll
            for (int h = 0; h < 2; h++) {
                const int row = m0 + wm * 64 + mt * 16 + (lane >> 2) + h * 8;
                const float br = (flags & F_BROW) ? bias[row] : 0.f;
                #pragma unroll
                for (int nt = 0; nt < 8; nt++) {
                    const int col = n0 + wncol + nt * 8 + (lane & 3) * 2;
                    const size_t idx = (size_t)row * ldc + col;
                    __half2 p2 = __floats2half2_rn(acc[mt][nt][h * 2 + 0] + br,
                                                   acc[mt][nt][h * 2 + 1] + br);
                    *(uint32_t*)(Ch + (size_t)bz * sC + idx) = *(uint32_t*)&p2;
                }
            }
    }
}

// ---------------------------------------------------------------------------
// fused weight prep: Wq/Wk -> bf16 hi/lo, Wv -> single f16
// ---------------------------------------------------------------------------
__global__ void prep_split(const float* __restrict__ Wq, const float* __restrict__ Wk,
                           const float* __restrict__ Wv,
                           __nv_bfloat16* __restrict__ Wq_h, __nv_bfloat16* __restrict__ Wq_l,
                           __nv_bfloat16* __restrict__ Wk_h, __nv_bfloat16* __restrict__ Wk_l,
                           __half* __restrict__ Wv_f)
{
    const int i = blockIdx.x * blockDim.x + threadIdx.x;
    const int nqk = 256 * 512;
    if (i < 2 * nqk) {
        const float* src = (i < nqk) ? Wq : Wk;
        __nv_bfloat16* H = (i < nqk) ? Wq_h : Wk_h;
        __nv_bfloat16* L = (i < nqk) ? Wq_l : Wk_l;
        const int j = (i < nqk) ? i : i - nqk;
        const float v = src[j];
        const __nv_bfloat16 h = __float2bfloat16_rn(v);
        H[j] = h;
        L[j] = __float2bfloat16_rn(v - __bfloat162float(h));
    } else if (i < 2 * nqk + 512 * 512) {
        const int j = i - 2 * nqk;
        Wv_f[j] = __float2half_rn(Wv[j]);
    }
}

// ---------------------------------------------------------------------------
// fused transpose: Q,K -> bf16 hi/lo [N][C]; V -> single f16 [N][C]
// ---------------------------------------------------------------------------
__global__ __launch_bounds__(256)
void transpose_all(const float* __restrict__ Q, const float* __restrict__ Kin,
                   const float* __restrict__ V,
                   __nv_bfloat16* __restrict__ Qh, __nv_bfloat16* __restrict__ Ql,
                   __nv_bfloat16* __restrict__ Kh, __nv_bfloat16* __restrict__ Kl,
                   __half* __restrict__ Vt,
                   int rows, int cols, int batch)
{
    __shared__ float t[32][33];
    const int z = blockIdx.z;
    const int tsel = z / batch, bz = z % batch;
    const float* X = (tsel == 0) ? Q : (tsel == 1) ? Kin : V;
    const size_t bo = (size_t)bz * rows * cols;
    X += bo;
    const int x0 = blockIdx.x * 32;
    const int y0 = blockIdx.y * 32;
    const int tx = threadIdx.x & 31, ty = threadIdx.x >> 5;

    #pragma unroll
    for (int j = 0; j < 32; j += 8)
        t[ty + j][tx] = X[(size_t)(y0 + ty + j) * cols + x0 + tx];
    __syncthreads();

    if (tsel < 2) {
        __nv_bfloat16* Th = ((tsel == 0) ? Qh : Kh) + bo;
        __nv_bfloat16* Tl = ((tsel == 0) ? Ql : Kl) + bo;
        #pragma unroll
        for (int j = 0; j < 32; j += 8) {
            const float v = t[tx][ty + j];
            const __nv_bfloat16 h = __float2bfloat16_rn(v);
            const __nv_bfloat16 l = __float2bfloat16_rn(v - __bfloat162float(h));
            const size_t idx = (size_t)(x0 + ty + j) * rows + y0 + tx;
            Th[idx] = h;
            Tl[idx] = l;
        }
    } else {
        __half* Tv = Vt + bo;
        #pragma unroll
        for (int j = 0; j < 32; j += 8) {
            const size_t idx = (size_t)(x0 + ty + j) * rows + y0 + tx;
            Tv[idx] = __float2half_rn(t[tx][ty + j]);
        }
    }
}

// ---------------------------------------------------------------------------
// row softmax; writes attention as single f16
// ---------------------------------------------------------------------------
__device__ __forceinline__ float fexp(float x) {  // exp(x), x <= 0
    float t = fmaxf(x * 1.44269504f, -126.f);
    float fi = floorf(t);
    float f = t - fi;
    float p = 1.5465324e-4f;
    p = p * f + 1.3333558e-3f;
    p = p * f + 9.6181291e-3f;
    p = p * f + 5.5504109e-2f;
    p = p * f + 2.4022651e-1f;
    p = p * f + 6.9314718e-1f;
    p = p * f + 1.0f;
    return p * __int_as_float(((int)fi + 127) << 23);
}

__global__ __launch_bounds__(256)
void softmax_row(const float* __restrict__ E, __half* __restrict__ A, int Ncols)
{
    const int row = blockIdx.x;
    const int bz = blockIdx.y;
    const size_t base = ((size_t)bz * gridDim.x + row) * Ncols;
    const int tid = threadIdx.x, wid = tid >> 5, lid = tid & 31;

    __shared__ float sbuf[8];

    float x[16];
    const float4* rp = (const float4*)(E + base);
    #pragma unroll
    for (int k = 0; k < 4; k++) {
        float4 v4 = rp[tid + k * 256];
        x[k * 4 + 0] = v4.x; x[k * 4 + 1] = v4.y; x[k * 4 + 2] = v4.z; x[k * 4 + 3] = v4.w;
    }

    float m = x[0];
    #pragma unroll
    for (int i = 1; i < 16; i++) m = fmaxf(m, x[i]);
    #pragma unroll
    for (int o = 16; o; o >>= 1) m = fmaxf(m, __shfl_xor_sync(0xffffffffu, m, o));
    if (lid == 0) sbuf[wid] = m;
    __syncthreads();
    float mx = sbuf[0];
    #pragma unroll
    for (int i = 1; i < 8; i++) mx = fmaxf(mx, sbuf[i]);
    __syncthreads();

    float s = 0.f;
    #pragma unroll
    for (int i = 0; i < 16; i++) { x[i] = fexp(x[i] - mx); s += x[i]; }
    #pragma unroll
    for (int o = 16; o; o >>= 1) s += __shfl_xor_sync(0xffffffffu, s, o);
    if (lid == 0) sbuf[wid] = s;
    __syncthreads();
    float tot = 0.f;
    #pragma unroll
    for (int i = 0; i < 8; i++) tot += sbuf[i];
    const float inv = 1.f / tot;

    #pragma unroll
    for (int k = 0; k < 4; k++) {
        uint32_t hp[2];
        #pragma unroll
        for (int j = 0; j < 2; j++) {
            __half2 p2 = __floats2half2_rn(x[k * 4 + 2 * j] * inv, x[k * 4 + 2 * j + 1] * inv);
            hp[j] = *(uint32_t*)&p2;
        }
        const size_t idx = base + (size_t)(tid + k * 256) * 4;
        *(uint2*)(A + idx) = *(const uint2*)hp;
    }
}

// ---------------------------------------------------------------------------
extern "C" void kernel_launch(void* const* d_in, const int* in_sizes, int n_in,
                              void* d_out, int out_size)
{
    const float* Q     = (const float*)d_in[0];
    const float* Kin   = (const float*)d_in[1];
    const float* V     = (const float*)d_in[2];
    const float* Wq    = (const float*)d_in[3];
    const float* bq    = (const float*)d_in[4];
    const float* Wk    = (const float*)d_in[5];
    const float* bk    = (const float*)d_in[6];
    const float* Wv    = (const float*)d_in[7];
    const float* bv    = (const float*)d_in[8];
    const float* gamma = (const float*)d_in[9];
    float* out = (float*)d_out;

    __nv_bfloat16 *Qt_h, *Qt_l, *Kt_h, *Kt_l;
    __half *Vt, *Wv_f, *v, *a;
    __nv_bfloat16 *Wq_h, *Wq_l, *Wk_h, *Wk_l;
    __nv_bfloat16 *qt_h, *qt_l, *kt_h, *kt_l;
    float* e;
    cudaGetSymbolAddress((void**)&Qt_h, g_Qt_h); cudaGetSymbolAddress((void**)&Qt_l, g_Qt_l);
    cudaGetSymbolAddress((void**)&Kt_h, g_Kt_h); cudaGetSymbolAddress((void**)&Kt_l, g_Kt_l);
    cudaGetSymbolAddress((void**)&Vt,   g_Vt);
    cudaGetSymbolAddress((void**)&Wq_h, g_Wq_h); cudaGetSymbolAddress((void**)&Wq_l, g_Wq_l);
    cudaGetSymbolAddress((void**)&Wk_h, g_Wk_h); cudaGetSymbolAddress((void**)&Wk_l, g_Wk_l);
    cudaGetSymbolAddress((void**)&Wv_f, g_Wv);
    cudaGetSymbolAddress((void**)&qt_h, g_qt_h); cudaGetSymbolAddress((void**)&qt_l, g_qt_l);
    cudaGetSymbolAddress((void**)&kt_h, g_kt_h); cudaGetSymbolAddress((void**)&kt_l, g_kt_l);
    cudaGetSymbolAddress((void**)&v,    g_v);
    cudaGetSymbolAddress((void**)&a,    g_a);
    cudaGetSymbolAddress((void**)&e,    g_e);

    const int B = B_, C = C_, CH = CH_, N = N_;

    cudaFuncSetAttribute(tgemm_kernel, cudaFuncAttributeMaxDynamicSharedMemorySize, TG_SMEM);
    cudaFuncSetAttribute(tgemm_h<1>, cudaFuncAttributeMaxDynamicSharedMemorySize,
                         2 * (2 * A_TILE + B_TILE));
    cudaFuncSetAttribute(tgemm_h<0>, cudaFuncAttributeMaxDynamicSharedMemorySize,
                         2 * (A_TILE + B_TILE));

    // 0: weight prep (Wq/Wk bf16 hi/lo, Wv single f16)
    const int nsplit = 2 * CH * C + C * C;
    prep_split<<<(nsplit + 255) / 256, 256>>>(Wq, Wk, Wv, Wq_h, Wq_l, Wk_h, Wk_l, Wv_f);

    // 1: input transpose (Q,K bf16 hi/lo; V single f16)
    transpose_all<<<dim3(N / 32, C / 32, 3 * B), 256>>>(
        Q, Kin, V, Qt_h, Qt_l, Kt_h, Kt_l, Vt, C, N, B);

    // 2: qt[n][ch] = Qt . Wq^T + bq[ch]   (bf16 split-3, split out)
    tgemm_kernel<<<dim3(CH / 256, N / 128, B), 256, TG_SMEM>>>(
        Qt_h, Qt_l, Wq_h, Wq_l, nullptr, qt_h, qt_l, bq,
        C, CH, (size_t)N * C, 0, (size_t)N * CH, F_SPLIT | F_BCOL);
    // 3: kt
    tgemm_kernel<<<dim3(CH / 256, N / 128, B), 256, TG_SMEM>>>(
        Kt_h, Kt_l, Wk_h, Wk_l, nullptr, kt_h, kt_l, bk,
        C, CH, (size_t)N * C, 0, (size_t)N * CH, F_SPLIT | F_BCOL);

    // 4: v[c][n] = Wv . Vt^T + bv[c]   (1-pass f16, f32 accum, f16 out)
    tgemm_h<0><<<dim3(N / 256, C / 128, B), 256, 2 * (A_TILE + B_TILE)>>>(
        Wv_f, nullptr, Vt, nullptr, v, bv, nullptr, nullptr,
        C, N, 0, (size_t)N * C, (size_t)C * N, 0, F_BROW);

    // 5 (profiled): e[n][m] = qt . kt^T   (bf16 split-3, f32 out)
    tgemm_kernel<<<dim3(N / 256, N / 128, B), 256, TG_SMEM>>>(
        qt_h, qt_l, kt_h, kt_l, e, nullptr, nullptr, nullptr,
        CH, N, (size_t)N * CH, (size_t)N * CH, (size_t)N * N, 0);

    // 6: attention = softmax_m(e) -> single f16
    softmax_row<<<dim3(N, B), 256>>>(e, a, N);

    // 7: out[c][n] = gamma * (v . attn^T) + V   (1-pass f16, f32 accum)
    tgemm_h<0><<<dim3(N / 256, C / 128, B), 256, 2 * (A_TILE + B_TILE)>>>(
        v, nullptr, a, out, nullptr, nullptr, V, gamma,
        N, N, (size_t)C * N, (size_t)N * N, (size_t)C * N, (size_t)C * N, F_RES);
}

// round 16
// speedup vs baseline: 1.1250x; 1.0150x over previous
#include <cuda_runtime.h>
#include <cuda_bf16.h>
#include <cuda_fp16.h>
#include <cstdint>

// ---------------------------------------------------------------------------
// AttentionModule via mma.sync m16n8k16 (legacy HMMA; tcgen05 ptxas-gated off;
// HW cap ~585 MACs/cyc/SM (rt=14/SMSP), f16-accum NOT faster (r11)).
// Pass-minimal schedule (proven floor):
//   q/k projections: bf16 split-3;  energy: bf16 split-3, f32 out
//   v projection:    1-pass f16;    out: 1-pass f16, gamma*acc + V
//   softmax:         poly-exp, row in regs, attention stored single f16
// Round 15: two-stream launch graph — v-proj overlaps q/k partial waves;
// per-batch softmax on s2 hides under energy/out MMA time (fork/join events,
// graph-capturable multi-stream pattern). Kernels byte-identical to r14.
// ---------------------------------------------------------------------------

static const int B_ = 4, C_ = 512, CH_ = 256, N_ = 4096;

// ---------------- scratch ----------------
__device__ __align__(256) __nv_bfloat16 g_Qt_h[4L * 4096 * 512];
__device__ __align__(256) __nv_bfloat16 g_Qt_l[4L * 4096 * 512];
__device__ __align__(256) __nv_bfloat16 g_Kt_h[4L * 4096 * 512];
__device__ __align__(256) __nv_bfloat16 g_Kt_l[4L * 4096 * 512];
__device__ __align__(256) __half        g_Vt  [4L * 4096 * 512];
__device__ __align__(256) __nv_bfloat16 g_Wq_h[256 * 512];
__device__ __align__(256) __nv_bfloat16 g_Wq_l[256 * 512];
__device__ __align__(256) __nv_bfloat16 g_Wk_h[256 * 512];
__device__ __align__(256) __nv_bfloat16 g_Wk_l[256 * 512];
__device__ __align__(256) __half        g_Wv  [512 * 512];
__device__ __align__(256) __nv_bfloat16 g_qt_h[4L * 4096 * 256];
__device__ __align__(256) __nv_bfloat16 g_qt_l[4L * 4096 * 256];
__device__ __align__(256) __nv_bfloat16 g_kt_h[4L * 4096 * 256];
__device__ __align__(256) __nv_bfloat16 g_kt_l[4L * 4096 * 256];
__device__ __align__(256) __half        g_v   [4L * 512 * 4096];
__device__ __align__(256) float         g_e   [4L * 4096 * 4096];
__device__ __align__(256) __half        g_a   [4L * 4096 * 4096];

// ---------------- helpers ----------------
__device__ __forceinline__ uint32_t smem_to_u32(const void* p) {
    uint32_t a;
    asm("{ .reg .u64 t; cvta.to.shared.u64 t, %1; cvt.u32.u64 %0, t; }" : "=r"(a) : "l"(p));
    return a;
}
__device__ __forceinline__ void cp16(uint32_t dst, const void* src) {
    asm volatile("cp.async.cg.shared.global [%0], [%1], 16;" :: "r"(dst), "l"(src) : "memory");
}
__device__ __forceinline__ void cp_commit() { asm volatile("cp.async.commit_group;" ::: "memory"); }
__device__ __forceinline__ void cp_wait1()  { asm volatile("cp.async.wait_group 1;" ::: "memory"); }
__device__ __forceinline__ void cp_wait0()  { asm volatile("cp.async.wait_group 0;" ::: "memory"); }

__device__ __forceinline__ void ldsm4(uint32_t* r, uint32_t a) {
    asm volatile("ldmatrix.sync.aligned.m8n8.x4.shared.b16 {%0,%1,%2,%3}, [%4];"
                 : "=r"(r[0]), "=r"(r[1]), "=r"(r[2]), "=r"(r[3]) : "r"(a));
}
__device__ __forceinline__ void mma_bf16(float* c, const uint32_t* a, const uint32_t* b) {
    asm volatile("mma.sync.aligned.m16n8k16.row.col.f32.bf16.bf16.f32 "
                 "{%0,%1,%2,%3}, {%4,%5,%6,%7}, {%8,%9}, {%0,%1,%2,%3};"
                 : "+f"(c[0]), "+f"(c[1]), "+f"(c[2]), "+f"(c[3])
                 : "r"(a[0]), "r"(a[1]), "r"(a[2]), "r"(a[3]), "r"(b[0]), "r"(b[1]));
}
__device__ __forceinline__ void mma_f16(float* c, const uint32_t* a, const uint32_t* b) {
    asm volatile("mma.sync.aligned.m16n8k16.row.col.f32.f16.f16.f32 "
                 "{%0,%1,%2,%3}, {%4,%5,%6,%7}, {%8,%9}, {%0,%1,%2,%3};"
                 : "+f"(c[0]), "+f"(c[1]), "+f"(c[2]), "+f"(c[3])
                 : "r"(a[0]), "r"(a[1]), "r"(a[2]), "r"(a[3]), "r"(b[0]), "r"(b[1]));
}

#define LDR     80
#define A_TILE  (128 * LDR)
#define B_TILE  (256 * LDR)

enum { F_SPLIT = 1, F_BROW = 2, F_BCOL = 4, F_RES = 8 };

// ---------------------------------------------------------------------------
// bf16 split-3 tgemm (q/k projections + energy). CTA 128x256, warp 64x64.
// ---------------------------------------------------------------------------
#define STAGE_S (2 * A_TILE + 2 * B_TILE)   // 61440
#define TG_SMEM (2 * STAGE_S)               // 122880

__global__ void __launch_bounds__(256, 1)
tgemm_kernel(const __nv_bfloat16* __restrict__ Ah, const __nv_bfloat16* __restrict__ Al,
             const __nv_bfloat16* __restrict__ Bh, const __nv_bfloat16* __restrict__ Bl,
             float* __restrict__ Cf, __nv_bfloat16* __restrict__ Chi, __nv_bfloat16* __restrict__ Clo,
             const float* __restrict__ bias,
             int Kd, int ldc, size_t sA, size_t sB, size_t sC, int flags)
{
    extern __shared__ char smem[];
    const uint32_t sm0 = smem_to_u32(smem);
    const int tid = threadIdx.x, wid = tid >> 5, lane = tid & 31;
    const int bz = blockIdx.z;
    const int m0 = blockIdx.y * 128;
    const int n0 = blockIdx.x * 256;

    const size_t ldkB = (size_t)Kd * 2;
    const int lr = tid >> 2, seg = tid & 3;
    const char* gA_h = (const char*)(Ah + (size_t)bz * sA) + (size_t)(m0 + lr) * ldkB + seg * 16;
    const char* gA_l = (const char*)(Al + (size_t)bz * sA) + (size_t)(m0 + lr) * ldkB + seg * 16;
    const char* gB_h = (const char*)(Bh + (size_t)bz * sB) + (size_t)(n0 + lr) * ldkB + seg * 16;
    const char* gB_l = (const char*)(Bl + (size_t)bz * sB) + (size_t)(n0 + lr) * ldkB + seg * 16;
    const size_t g64 = 64 * ldkB;
    const uint32_t dthr = sm0 + (uint32_t)lr * LDR + (uint32_t)seg * 16;

    const int nch = Kd >> 5;
    const int wm = wid & 1;
    const int wncol = (wid >> 1) * 64;
    const uint32_t a_off = (uint32_t)((lane & 15) * LDR + (lane >> 4) * 16);
    const uint32_t b_off = (uint32_t)(((lane & 7) + ((lane >> 4) & 1) * 8) * LDR + ((lane >> 3) & 1) * 16);

    float acc[4][8][4];
    #pragma unroll
    for (int i = 0; i < 4; i++)
        #pragma unroll
        for (int j = 0; j < 8; j++)
            #pragma unroll
            for (int k = 0; k < 4; k++) acc[i][j][k] = 0.f;

#define TG_LOAD(s, c) do { \
        const size_t _ko = (size_t)(c) * 64; \
        const uint32_t _d = dthr + (uint32_t)(s) * STAGE_S; \
        cp16(_d,                     gA_h + _ko); \
        cp16(_d + 64 * LDR,          gA_h + _ko + g64); \
        cp16(_d + A_TILE,            gA_l + _ko); \
        cp16(_d + A_TILE + 64 * LDR, gA_l + _ko + g64); \
        _Pragma("unroll") \
        for (int _j = 0; _j < 4; _j++) \
            cp16(_d + 2 * A_TILE + _j * 64 * LDR, gB_h + _ko + _j * g64); \
        _Pragma("unroll") \
        for (int _j = 0; _j < 4; _j++) \
            cp16(_d + 2 * A_TILE + B_TILE + _j * 64 * LDR, gB_l + _ko + _j * g64); \
        cp_commit(); \
    } while (0)

    TG_LOAD(0, 0);

    for (int c = 0; c < nch; c++) {
        const int s = c & 1;
        if (c + 1 < nch) { TG_LOAD(s ^ 1, c + 1); cp_wait1(); }
        else             { cp_wait0(); }
        __syncthreads();

        const uint32_t sb  = sm0 + (uint32_t)s * STAGE_S;
        const uint32_t sAh = sb, sAl = sb + A_TILE;
        const uint32_t sBh = sb + 2 * A_TILE, sBl = sBh + B_TILE;

        #pragma unroll
        for (int ks = 0; ks < 2; ks++) {
            const uint32_t ko = ks * 32;
            uint32_t bh[8][2], bl[8][2], af[4][4];
            #pragma unroll
            for (int p = 0; p < 4; p++) {
                uint32_t r[4];
                ldsm4(r, sBh + (uint32_t)(wncol + p * 16) * LDR + ko + b_off);
                bh[2 * p][0] = r[0]; bh[2 * p][1] = r[1];
                bh[2 * p + 1][0] = r[2]; bh[2 * p + 1][1] = r[3];
            }
            #pragma unroll
            for (int mt = 0; mt < 4; mt++)
                ldsm4(af[mt], sAh + (uint32_t)(wm * 64 + mt * 16) * LDR + ko + a_off);
            #pragma unroll
            for (int mt = 0; mt < 4; mt++)
                #pragma unroll
                for (int nt = 0; nt < 8; nt++) mma_bf16(acc[mt][nt], af[mt], bh[nt]);
            #pragma unroll
            for (int p = 0; p < 4; p++) {
                uint32_t r[4];
                ldsm4(r, sBl + (uint32_t)(wncol + p * 16) * LDR + ko + b_off);
                bl[2 * p][0] = r[0]; bl[2 * p][1] = r[1];
                bl[2 * p + 1][0] = r[2]; bl[2 * p + 1][1] = r[3];
            }
            #pragma unroll
            for (int mt = 0; mt < 4; mt++)
                #pragma unroll
                for (int nt = 0; nt < 8; nt++) mma_bf16(acc[mt][nt], af[mt], bl[nt]);
            #pragma unroll
            for (int mt = 0; mt < 4; mt++)
                ldsm4(af[mt], sAl + (uint32_t)(wm * 64 + mt * 16) * LDR + ko + a_off);
            #pragma unroll
            for (int mt = 0; mt < 4; mt++)
                #pragma unroll
                for (int nt = 0; nt < 8; nt++) mma_bf16(acc[mt][nt], af[mt], bh[nt]);
        }
        __syncthreads();
    }

    // epilogue
    #pragma unroll
    for (int mt = 0; mt < 4; mt++) {
        #pragma unroll
        for (int h = 0; h < 2; h++) {
            const int row = m0 + wm * 64 + mt * 16 + (lane >> 2) + h * 8;
            #pragma unroll
            for (int nt = 0; nt < 8; nt++) {
                const int col = n0 + wncol + nt * 8 + (lane & 3) * 2;
                float v0 = acc[mt][nt][h * 2 + 0];
                float v1 = acc[mt][nt][h * 2 + 1];
                if (flags & F_BCOL) { v0 += bias[col]; v1 += bias[col + 1]; }
                const size_t idx = (size_t)row * ldc + col;
                if (flags & F_SPLIT) {
                    __nv_bfloat16 h0 = __float2bfloat16_rn(v0);
                    __nv_bfloat16 h1 = __float2bfloat16_rn(v1);
                    __nv_bfloat16 l0 = __float2bfloat16_rn(v0 - __bfloat162float(h0));
                    __nv_bfloat16 l1 = __float2bfloat16_rn(v1 - __bfloat162float(h1));
                    uint32_t hp = (uint32_t)__bfloat16_as_ushort(h0) | ((uint32_t)__bfloat16_as_ushort(h1) << 16);
                    uint32_t lp = (uint32_t)__bfloat16_as_ushort(l0) | ((uint32_t)__bfloat16_as_ushort(l1) << 16);
                    *(uint32_t*)(Chi + (size_t)bz * sC + idx) = hp;
                    *(uint32_t*)(Clo + (size_t)bz * sC + idx) = lp;
                } else {
                    float2 o;
                    o.x = v0;
                    o.y = v1;
                    *(float2*)(Cf + (size_t)bz * sC + idx) = o;
                }
            }
        }
    }
}

// ---------------------------------------------------------------------------
// f16 GEMM, TWO=1: D = (Ah+Al).B^T (2 passes); TWO=0: D = Ah.B^T (1 pass).
// f32 accumulators. CTA 128x256, warp 64x64.
// ---------------------------------------------------------------------------
template <int TWO>
__global__ void __launch_bounds__(256, 1)
tgemm_h(const __half* __restrict__ Ah, const __half* __restrict__ Al,
        const __half* __restrict__ Bs,
        float* __restrict__ Cf, __half* __restrict__ Ch,
        const float* __restrict__ bias, const float* __restrict__ R,
        const float* __restrict__ gammap,
        int Kd, int ldc, size_t sA, size_t sB, size_t sC, size_t sR, int flags)
{
    constexpr int H_STAGE = (TWO ? 2 : 1) * A_TILE + B_TILE;
    extern __shared__ char smem[];
    const uint32_t sm0 = smem_to_u32(smem);
    const int tid = threadIdx.x, wid = tid >> 5, lane = tid & 31;
    const int bz = blockIdx.z;
    const int m0 = blockIdx.y * 128;
    const int n0 = blockIdx.x * 256;

    const size_t ldkB = (size_t)Kd * 2;
    const int lr = tid >> 2, seg = tid & 3;
    const char* gA_h = (const char*)(Ah + (size_t)bz * sA) + (size_t)(m0 + lr) * ldkB + seg * 16;
    const char* gA_l = TWO ? (const char*)(Al + (size_t)bz * sA) + (size_t)(m0 + lr) * ldkB + seg * 16 : nullptr;
    const char* gB   = (const char*)(Bs + (size_t)bz * sB) + (size_t)(n0 + lr) * ldkB + seg * 16;
    const size_t g64 = 64 * ldkB;
    const uint32_t dthr = sm0 + (uint32_t)lr * LDR + (uint32_t)seg * 16;
    const uint32_t boff_b = (TWO ? 2 : 1) * A_TILE;

    const int nch = Kd >> 5;
    const int wm = wid & 1;
    const int wncol = (wid >> 1) * 64;
    const uint32_t a_off = (uint32_t)((lane & 15) * LDR + (lane >> 4) * 16);
    const uint32_t b_off = (uint32_t)(((lane & 7) + ((lane >> 4) & 1) * 8) * LDR + ((lane >> 3) & 1) * 16);

    float acc[4][8][4];
    #pragma unroll
    for (int i = 0; i < 4; i++)
        #pragma unroll
        for (int j = 0; j < 8; j++)
            #pragma unroll
            for (int k = 0; k < 4; k++) acc[i][j][k] = 0.f;

#define TH_LOAD(s, c) do { \
        const size_t _ko = (size_t)(c) * 64; \
        const uint32_t _d = dthr + (uint32_t)(s) * H_STAGE; \
        cp16(_d,            gA_h + _ko); \
        cp16(_d + 64 * LDR, gA_h + _ko + g64); \
        if (TWO) { \
            cp16(_d + A_TILE,            gA_l + _ko); \
            cp16(_d + A_TILE + 64 * LDR, gA_l + _ko + g64); \
        } \
        _Pragma("unroll") \
        for (int _j = 0; _j < 4; _j++) \
            cp16(_d + boff_b + _j * 64 * LDR, gB + _ko + _j * g64); \
        cp_commit(); \
    } while (0)

    TH_LOAD(0, 0);

    for (int c = 0; c < nch; c++) {
        const int s = c & 1;
        if (c + 1 < nch) { TH_LOAD(s ^ 1, c + 1); cp_wait1(); }
        else             { cp_wait0(); }
        __syncthreads();

        const uint32_t sb  = sm0 + (uint32_t)s * H_STAGE;
        const uint32_t sAh = sb, sAl = sb + A_TILE, sB_ = sb + boff_b;

        #pragma unroll
        for (int ks = 0; ks < 2; ks++) {
            const uint32_t ko = ks * 32;
            uint32_t bf[8][2], af[4][4];
            #pragma unroll
            for (int p = 0; p < 4; p++) {
                uint32_t r[4];
                ldsm4(r, sB_ + (uint32_t)(wncol + p * 16) * LDR + ko + b_off);
                bf[2 * p][0] = r[0]; bf[2 * p][1] = r[1];
                bf[2 * p + 1][0] = r[2]; bf[2 * p + 1][1] = r[3];
            }
            #pragma unroll
            for (int mt = 0; mt < 4; mt++)
                ldsm4(af[mt], sAh + (uint32_t)(wm * 64 + mt * 16) * LDR + ko + a_off);
            #pragma unroll
            for (int mt = 0; mt < 4; mt++)
                #pragma unroll
                for (int nt = 0; nt < 8; nt++) mma_f16(acc[mt][nt], af[mt], bf[nt]);
            if (TWO) {
                #pragma unroll
                for (int mt = 0; mt < 4; mt++)
                    ldsm4(af[mt], sAl + (uint32_t)(wm * 64 + mt * 16) * LDR + ko + a_off);
                #pragma unroll
                for (int mt = 0; mt < 4; mt++)
                    #pragma unroll
                    for (int nt = 0; nt < 8; nt++) mma_f16(acc[mt][nt], af[mt], bf[nt]);
            }
        }
        __syncthreads();
    }

    if (flags & F_RES) {
        const float g = *gammap;
        #pragma unroll
        for (int mt = 0; mt < 4; mt++)
            #pragma unroll
            for (int h = 0; h < 2; h++) {
                const int row = m0 + wm * 64 + mt * 16 + (lane >> 2) + h * 8;
                #pragma unroll
                for (int nt = 0; nt < 8; nt++) {
                    const int col = n0 + wncol + nt * 8 + (lane & 3) * 2;
                    const size_t idx = (size_t)row * ldc + col;
                    const float2 rv = *(const float2*)(R + (size_t)bz * sR + idx);
                    float2 o;
                    o.x = g * acc[mt][nt][h * 2 + 0] + rv.x;
                    o.y = g * acc[mt][nt][h * 2 + 1] + rv.y;
                    *(float2*)(Cf + (size_t)bz * sC + idx) = o;
                }
            }
    } else {
        #pragma unroll
        for (int mt = 0; mt < 4; mt++)
            #pragma unroll
            for (int h = 0; h < 2; h++) {
                const int row = m0 + wm * 64 + mt * 16 + (lane >> 2) + h * 8;
                const float br = (flags & F_BROW) ? bias[row] : 0.f;
                #pragma unroll
                for (int nt = 0; nt < 8; nt++) {
                    const int col = n0 + wncol + nt * 8 + (lane & 3) * 2;
                    const size_t idx = (size_t)row * ldc + col;
                    __half2 p2 = __floats2half2_rn(acc[mt][nt][h * 2 + 0] + br,
                                                   acc[mt][nt][h * 2 + 1] + br);
                    *(uint32_t*)(Ch + (size_t)bz * sC + idx) = *(uint32_t*)&p2;
                }
            }
    }
}

// ---------------------------------------------------------------------------
// fused weight prep: Wq/Wk -> bf16 hi/lo, Wv -> single f16
// ---------------------------------------------------------------------------
__global__ void prep_split(const float* __restrict__ Wq, const float* __restrict__ Wk,
                           const float* __restrict__ Wv,
                           __nv_bfloat16* __restrict__ Wq_h, __nv_bfloat16* __restrict__ Wq_l,
                           __nv_bfloat16* __restrict__ Wk_h, __nv_bfloat16* __restrict__ Wk_l,
                           __half* __restrict__ Wv_f)
{
    const int i = blockIdx.x * blockDim.x + threadIdx.x;
    const int nqk = 256 * 512;
    if (i < 2 * nqk) {
        const float* src = (i < nqk) ? Wq : Wk;
        __nv_bfloat16* H = (i < nqk) ? Wq_h : Wk_h;
        __nv_bfloat16* L = (i < nqk) ? Wq_l : Wk_l;
        const int j = (i < nqk) ? i : i - nqk;
        const float v = src[j];
        const __nv_bfloat16 h = __float2bfloat16_rn(v);
        H[j] = h;
        L[j] = __float2bfloat16_rn(v - __bfloat162float(h));
    } else if (i < 2 * nqk + 512 * 512) {
        const int j = i - 2 * nqk;
        Wv_f[j] = __float2half_rn(Wv[j]);
    }
}

// ---------------------------------------------------------------------------
// fused transpose: Q,K -> bf16 hi/lo [N][C]; V -> single f16 [N][C]
// ---------------------------------------------------------------------------
__global__ __launch_bounds__(256)
void transpose_all(const float* __restrict__ Q, const float* __restrict__ Kin,
                   const float* __restrict__ V,
                   __nv_bfloat16* __restrict__ Qh, __nv_bfloat16* __restrict__ Ql,
                   __nv_bfloat16* __restrict__ Kh, __nv_bfloat16* __restrict__ Kl,
                   __half* __restrict__ Vt,
                   int rows, int cols, int batch)
{
    __shared__ float t[32][33];
    const int z = blockIdx.z;
    const int tsel = z / batch, bz = z % batch;
    const float* X = (tsel == 0) ? Q : (tsel == 1) ? Kin : V;
    const size_t bo = (size_t)bz * rows * cols;
    X += bo;
    const int x0 = blockIdx.x * 32;
    const int y0 = blockIdx.y * 32;
    const int tx = threadIdx.x & 31, ty = threadIdx.x >> 5;

    #pragma unroll
    for (int j = 0; j < 32; j += 8)
        t[ty + j][tx] = X[(size_t)(y0 + ty + j) * cols + x0 + tx];
    __syncthreads();

    if (tsel < 2) {
        __nv_bfloat16* Th = ((tsel == 0) ? Qh : Kh) + bo;
        __nv_bfloat16* Tl = ((tsel == 0) ? Ql : Kl) + bo;
        #pragma unroll
        for (int j = 0; j < 32; j += 8) {
            const float v = t[tx][ty + j];
            const __nv_bfloat16 h = __float2bfloat16_rn(v);
            const __nv_bfloat16 l = __float2bfloat16_rn(v - __bfloat162float(h));
            const size_t idx = (size_t)(x0 + ty + j) * rows + y0 + tx;
            Th[idx] = h;
            Tl[idx] = l;
        }
    } else {
        __half* Tv = Vt + bo;
        #pragma unroll
        for (int j = 0; j < 32; j += 8) {
            const size_t idx = (size_t)(x0 + ty + j) * rows + y0 + tx;
            Tv[idx] = __float2half_rn(t[tx][ty + j]);
        }
    }
}

// ---------------------------------------------------------------------------
// row softmax; writes attention as single f16 (grid (N,1); E/A pre-offset)
// ---------------------------------------------------------------------------
__device__ __forceinline__ float fexp(float x) {  // exp(x), x <= 0
    float t = fmaxf(x * 1.44269504f, -126.f);
    float fi = floorf(t);
    float f = t - fi;
    float p = 1.5465324e-4f;
    p = p * f + 1.3333558e-3f;
    p = p * f + 9.6181291e-3f;
    p = p * f + 5.5504109e-2f;
    p = p * f + 2.4022651e-1f;
    p = p * f + 6.9314718e-1f;
    p = p * f + 1.0f;
    return p * __int_as_float(((int)fi + 127) << 23);
}

__global__ __launch_bounds__(256)
void softmax_row(const float* __restrict__ E, __half* __restrict__ A, int Ncols)
{
    const int row = blockIdx.x;
    const size_t base = (size_t)row * Ncols;
    const int tid = threadIdx.x, wid = tid >> 5, lid = tid & 31;

    __shared__ float sbuf[8];

    float x[16];
    const float4* rp = (const float4*)(E + base);
    #pragma unroll
    for (int k = 0; k < 4; k++) {
        float4 v4 = rp[tid + k * 256];
        x[k * 4 + 0] = v4.x; x[k * 4 + 1] = v4.y; x[k * 4 + 2] = v4.z; x[k * 4 + 3] = v4.w;
    }

    float m = x[0];
    #pragma unroll
    for (int i = 1; i < 16; i++) m = fmaxf(m, x[i]);
    #pragma unroll
    for (int o = 16; o; o >>= 1) m = fmaxf(m, __shfl_xor_sync(0xffffffffu, m, o));
    if (lid == 0) sbuf[wid] = m;
    __syncthreads();
    float mx = sbuf[0];
    #pragma unroll
    for (int i = 1; i < 8; i++) mx = fmaxf(mx, sbuf[i]);
    __syncthreads();

    float s = 0.f;
    #pragma unroll
    for (int i = 0; i < 16; i++) { x[i] = fexp(x[i] - mx); s += x[i]; }
    #pragma unroll
    for (int o = 16; o; o >>= 1) s += __shfl_xor_sync(0xffffffffu, s, o);
    if (lid == 0) sbuf[wid] = s;
    __syncthreads();
    float tot = 0.f;
    #pragma unroll
    for (int i = 0; i < 8; i++) tot += sbuf[i];
    const float inv = 1.f / tot;

    #pragma unroll
    for (int k = 0; k < 4; k++) {
        uint32_t hp[2];
        #pragma unroll
        for (int j = 0; j < 2; j++) {
            __half2 p2 = __floats2half2_rn(x[k * 4 + 2 * j] * inv, x[k * 4 + 2 * j + 1] * inv);
            hp[j] = *(uint32_t*)&p2;
        }
        const size_t idx = base + (size_t)(tid + k * 256) * 4;
        *(uint2*)(A + idx) = *(const uint2*)hp;
    }
}

// ---------------------------------------------------------------------------
extern "C" void kernel_launch(void* const* d_in, const int* in_sizes, int n_in,
                              void* d_out, int out_size)
{
    const float* Q     = (const float*)d_in[0];
    const float* Kin   = (const float*)d_in[1];
    const float* V     = (const float*)d_in[2];
    const float* Wq    = (const float*)d_in[3];
    const float* bq    = (const float*)d_in[4];
    const float* Wk    = (const float*)d_in[5];
    const float* bk    = (const float*)d_in[6];
    const float* Wv    = (const float*)d_in[7];
    const float* bv    = (const float*)d_in[8];
    const float* gamma = (const float*)d_in[9];
    float* out = (float*)d_out;

    __nv_bfloat16 *Qt_h, *Qt_l, *Kt_h, *Kt_l;
    __half *Vt, *Wv_f, *v, *a;
    __nv_bfloat16 *Wq_h, *Wq_l, *Wk_h, *Wk_l;
    __nv_bfloat16 *qt_h, *qt_l, *kt_h, *kt_l;
    float* e;
    cudaGetSymbolAddress((void**)&Qt_h, g_Qt_h); cudaGetSymbolAddress((void**)&Qt_l, g_Qt_l);
    cudaGetSymbolAddress((void**)&Kt_h, g_Kt_h); cudaGetSymbolAddress((void**)&Kt_l, g_Kt_l);
    cudaGetSymbolAddress((void**)&Vt,   g_Vt);
    cudaGetSymbolAddress((void**)&Wq_h, g_Wq_h); cudaGetSymbolAddress((void**)&Wq_l, g_Wq_l);
    cudaGetSymbolAddress((void**)&Wk_h, g_Wk_h); cudaGetSymbolAddress((void**)&Wk_l, g_Wk_l);
    cudaGetSymbolAddress((void**)&Wv_f, g_Wv);
    cudaGetSymbolAddress((void**)&qt_h, g_qt_h); cudaGetSymbolAddress((void**)&qt_l, g_qt_l);
    cudaGetSymbolAddress((void**)&kt_h, g_kt_h); cudaGetSymbolAddress((void**)&kt_l, g_kt_l);
    cudaGetSymbolAddress((void**)&v,    g_v);
    cudaGetSymbolAddress((void**)&a,    g_a);
    cudaGetSymbolAddress((void**)&e,    g_e);

    const int B = B_, C = C_, CH = CH_, N = N_;
    const size_t NN = (size_t)N * N;
    const size_t CN = (size_t)C * N;

    // one-time host-side stream/event creation (no device memory involved)
    static cudaStream_t s2 = nullptr;
    static cudaEvent_t evT, evE, evS01, evS23;
    if (!s2) {
        cudaStreamCreateWithFlags(&s2, cudaStreamNonBlocking);
        cudaEventCreateWithFlags(&evT,   cudaEventDisableTiming);
        cudaEventCreateWithFlags(&evE,   cudaEventDisableTiming);
        cudaEventCreateWithFlags(&evS01, cudaEventDisableTiming);
        cudaEventCreateWithFlags(&evS23, cudaEventDisableTiming);
    }

    cudaFuncSetAttribute(tgemm_kernel, cudaFuncAttributeMaxDynamicSharedMemorySize, TG_SMEM);
    cudaFuncSetAttribute(tgemm_h<0>, cudaFuncAttributeMaxDynamicSharedMemorySize,
                         2 * (A_TILE + B_TILE));
    const int h0_smem = 2 * (A_TILE + B_TILE);

    // ---- main stream: weight prep + input transpose ----
    const int nsplit = 2 * CH * C + C * C;
    prep_split<<<(nsplit + 255) / 256, 256>>>(Wq, Wk, Wv, Wq_h, Wq_l, Wk_h, Wk_l, Wv_f);
    transpose_all<<<dim3(N / 32, C / 32, 3 * B), 256>>>(
        Q, Kin, V, Qt_h, Qt_l, Kt_h, Kt_l, Vt, C, N, B);

    // fork s2 after transpose
    cudaEventRecord(evT, 0);
    cudaStreamWaitEvent(s2, evT, 0);

    // ---- s2: v projection (independent of q/k; fills idle SMs) ----
    tgemm_h<0><<<dim3(N / 256, C / 128, B), 256, h0_smem, s2>>>(
        Wv_f, nullptr, Vt, nullptr, v, bv, nullptr, nullptr,
        C, N, 0, (size_t)N * C, CN, 0, F_BROW);

    // ---- main: q, k projections (bf16 split-3) ----
    tgemm_kernel<<<dim3(CH / 256, N / 128, B), 256, TG_SMEM>>>(
        Qt_h, Qt_l, Wq_h, Wq_l, nullptr, qt_h, qt_l, bq,
        C, CH, (size_t)N * C, 0, (size_t)N * CH, F_SPLIT | F_BCOL);
    tgemm_kernel<<<dim3(CH / 256, N / 128, B), 256, TG_SMEM>>>(
        Kt_h, Kt_l, Wk_h, Wk_l, nullptr, kt_h, kt_l, bk,
        C, CH, (size_t)N * C, 0, (size_t)N * CH, F_SPLIT | F_BCOL);

    // ---- main: energy (batched, bf16 split-3, f32 out) ----
    tgemm_kernel<<<dim3(N / 256, N / 128, B), 256, TG_SMEM>>>(
        qt_h, qt_l, kt_h, kt_l, e, nullptr, nullptr, nullptr,
        CH, N, (size_t)N * CH, (size_t)N * CH, NN, 0);
    cudaEventRecord(evE, 0);

    // ---- s2: per-batch softmax (hidden under energy tail / out MMA) ----
    cudaStreamWaitEvent(s2, evE, 0);
    softmax_row<<<dim3(N, 1), 256, 0, s2>>>(e + 0 * NN, a + 0 * NN, N);
    softmax_row<<<dim3(N, 1), 256, 0, s2>>>(e + 1 * NN, a + 1 * NN, N);
    cudaEventRecord(evS01, s2);
    softmax_row<<<dim3(N, 1), 256, 0, s2>>>(e + 2 * NN, a + 2 * NN, N);
    softmax_row<<<dim3(N, 1), 256, 0, s2>>>(e + 3 * NN, a + 3 * NN, N);
    cudaEventRecord(evS23, s2);

    // ---- main: out in two batch-pair launches (each 128 CTAs = 1 full wave) ----
    cudaStreamWaitEvent(0, evS01, 0);
    tgemm_h<0><<<dim3(N / 256, C / 128, 2), 256, h0_smem>>>(
        v, nullptr, a, out, nullptr, nullptr, V, gamma,
        N, N, CN, NN, CN, CN, F_RES);
    cudaStreamWaitEvent(0, evS23, 0);
    tgemm_h<0><<<dim3(N / 256, C / 128, 2), 256, h0_smem>>>(
        v + 2 * CN, nullptr, a + 2 * NN, out + 2 * CN, nullptr, nullptr,
        V + 2 * CN, gamma,
        N, N, CN, NN, CN, CN, F_RES);
}

// round 17
// speedup vs baseline: 1.1335x; 1.0076x over previous
#include <cuda_runtime.h>
#include <cuda_bf16.h>
#include <cuda_fp16.h>
#include <cstdint>

// ---------------------------------------------------------------------------
// AttentionModule via mma.sync m16n8k16 (legacy HMMA; tcgen05 ptxas-gated off;
// HW cap ~585 MACs/cyc/SM (rt=14/SMSP), f16-accum NOT faster (r11)).
// Pass-minimal schedule (proven floor):
//   q/k projections: bf16 split-3;  energy: bf16 split-3, f32 out
//   v projection:    1-pass f16;    out: 1-pass f16, gamma*acc + V
// Round 17: energy split into half-batch launches so softmax (rebuilt:
// 128 thr/row, MLP=8) starts 170us earlier and drains into GEMM tails.
// GEMM CTAs fill the whole RF -> overlap only lives in launch tails.
// ---------------------------------------------------------------------------

static const int B_ = 4, C_ = 512, CH_ = 256, N_ = 4096;

// ---------------- scratch ----------------
__device__ __align__(256) __nv_bfloat16 g_Qt_h[4L * 4096 * 512];
__device__ __align__(256) __nv_bfloat16 g_Qt_l[4L * 4096 * 512];
__device__ __align__(256) __nv_bfloat16 g_Kt_h[4L * 4096 * 512];
__device__ __align__(256) __nv_bfloat16 g_Kt_l[4L * 4096 * 512];
__device__ __align__(256) __half        g_Vt  [4L * 4096 * 512];
__device__ __align__(256) __nv_bfloat16 g_Wq_h[256 * 512];
__device__ __align__(256) __nv_bfloat16 g_Wq_l[256 * 512];
__device__ __align__(256) __nv_bfloat16 g_Wk_h[256 * 512];
__device__ __align__(256) __nv_bfloat16 g_Wk_l[256 * 512];
__device__ __align__(256) __half        g_Wv  [512 * 512];
__device__ __align__(256) __nv_bfloat16 g_qt_h[4L * 4096 * 256];
__device__ __align__(256) __nv_bfloat16 g_qt_l[4L * 4096 * 256];
__device__ __align__(256) __nv_bfloat16 g_kt_h[4L * 4096 * 256];
__device__ __align__(256) __nv_bfloat16 g_kt_l[4L * 4096 * 256];
__device__ __align__(256) __half        g_v   [4L * 512 * 4096];
__device__ __align__(256) float         g_e   [4L * 4096 * 4096];
__device__ __align__(256) __half        g_a   [4L * 4096 * 4096];

// ---------------- helpers ----------------
__device__ __forceinline__ uint32_t smem_to_u32(const void* p) {
    uint32_t a;
    asm("{ .reg .u64 t; cvta.to.shared.u64 t, %1; cvt.u32.u64 %0, t; }" : "=r"(a) : "l"(p));
    return a;
}
__device__ __forceinline__ void cp16(uint32_t dst, const void* src) {
    asm volatile("cp.async.cg.shared.global [%0], [%1], 16;" :: "r"(dst), "l"(src) : "memory");
}
__device__ __forceinline__ void cp_commit() { asm volatile("cp.async.commit_group;" ::: "memory"); }
__device__ __forceinline__ void cp_wait1()  { asm volatile("cp.async.wait_group 1;" ::: "memory"); }
__device__ __forceinline__ void cp_wait0()  { asm volatile("cp.async.wait_group 0;" ::: "memory"); }

__device__ __forceinline__ void ldsm4(uint32_t* r, uint32_t a) {
    asm volatile("ldmatrix.sync.aligned.m8n8.x4.shared.b16 {%0,%1,%2,%3}, [%4];"
                 : "=r"(r[0]), "=r"(r[1]), "=r"(r[2]), "=r"(r[3]) : "r"(a));
}
__device__ __forceinline__ void mma_bf16(float* c, const uint32_t* a, const uint32_t* b) {
    asm volatile("mma.sync.aligned.m16n8k16.row.col.f32.bf16.bf16.f32 "
                 "{%0,%1,%2,%3}, {%4,%5,%6,%7}, {%8,%9}, {%0,%1,%2,%3};"
                 : "+f"(c[0]), "+f"(c[1]), "+f"(c[2]), "+f"(c[3])
                 : "r"(a[0]), "r"(a[1]), "r"(a[2]), "r"(a[3]), "r"(b[0]), "r"(b[1]));
}
__device__ __forceinline__ void mma_f16(float* c, const uint32_t* a, const uint32_t* b) {
    asm volatile("mma.sync.aligned.m16n8k16.row.col.f32.f16.f16.f32 "
                 "{%0,%1,%2,%3}, {%4,%5,%6,%7}, {%8,%9}, {%0,%1,%2,%3};"
                 : "+f"(c[0]), "+f"(c[1]), "+f"(c[2]), "+f"(c[3])
                 : "r"(a[0]), "r"(a[1]), "r"(a[2]), "r"(a[3]), "r"(b[0]), "r"(b[1]));
}

#define LDR     80
#define A_TILE  (128 * LDR)
#define B_TILE  (256 * LDR)

enum { F_SPLIT = 1, F_BROW = 2, F_BCOL = 4, F_RES = 8 };

// ---------------------------------------------------------------------------
// bf16 split-3 tgemm (q/k projections + energy). CTA 128x256, warp 64x64.
// ---------------------------------------------------------------------------
#define STAGE_S (2 * A_TILE + 2 * B_TILE)   // 61440
#define TG_SMEM (2 * STAGE_S)               // 122880

__global__ void __launch_bounds__(256, 1)
tgemm_kernel(const __nv_bfloat16* __restrict__ Ah, const __nv_bfloat16* __restrict__ Al,
             const __nv_bfloat16* __restrict__ Bh, const __nv_bfloat16* __restrict__ Bl,
             float* __restrict__ Cf, __nv_bfloat16* __restrict__ Chi, __nv_bfloat16* __restrict__ Clo,
             const float* __restrict__ bias,
             int Kd, int ldc, size_t sA, size_t sB, size_t sC, int flags)
{
    extern __shared__ char smem[];
    const uint32_t sm0 = smem_to_u32(smem);
    const int tid = threadIdx.x, wid = tid >> 5, lane = tid & 31;
    const int bz = blockIdx.z;
    const int m0 = blockIdx.y * 128;
    const int n0 = blockIdx.x * 256;

    const size_t ldkB = (size_t)Kd * 2;
    const int lr = tid >> 2, seg = tid & 3;
    const char* gA_h = (const char*)(Ah + (size_t)bz * sA) + (size_t)(m0 + lr) * ldkB + seg * 16;
    const char* gA_l = (const char*)(Al + (size_t)bz * sA) + (size_t)(m0 + lr) * ldkB + seg * 16;
    const char* gB_h = (const char*)(Bh + (size_t)bz * sB) + (size_t)(n0 + lr) * ldkB + seg * 16;
    const char* gB_l = (const char*)(Bl + (size_t)bz * sB) + (size_t)(n0 + lr) * ldkB + seg * 16;
    const size_t g64 = 64 * ldkB;
    const uint32_t dthr = sm0 + (uint32_t)lr * LDR + (uint32_t)seg * 16;

    const int nch = Kd >> 5;
    const int wm = wid & 1;
    const int wncol = (wid >> 1) * 64;
    const uint32_t a_off = (uint32_t)((lane & 15) * LDR + (lane >> 4) * 16);
    const uint32_t b_off = (uint32_t)(((lane & 7) + ((lane >> 4) & 1) * 8) * LDR + ((lane >> 3) & 1) * 16);

    float acc[4][8][4];
    #pragma unroll
    for (int i = 0; i < 4; i++)
        #pragma unroll
        for (int j = 0; j < 8; j++)
            #pragma unroll
            for (int k = 0; k < 4; k++) acc[i][j][k] = 0.f;

#define TG_LOAD(s, c) do { \
        const size_t _ko = (size_t)(c) * 64; \
        const uint32_t _d = dthr + (uint32_t)(s) * STAGE_S; \
        cp16(_d,                     gA_h + _ko); \
        cp16(_d + 64 * LDR,          gA_h + _ko + g64); \
        cp16(_d + A_TILE,            gA_l + _ko); \
        cp16(_d + A_TILE + 64 * LDR, gA_l + _ko + g64); \
        _Pragma("unroll") \
        for (int _j = 0; _j < 4; _j++) \
            cp16(_d + 2 * A_TILE + _j * 64 * LDR, gB_h + _ko + _j * g64); \
        _Pragma("unroll") \
        for (int _j = 0; _j < 4; _j++) \
            cp16(_d + 2 * A_TILE + B_TILE + _j * 64 * LDR, gB_l + _ko + _j * g64); \
        cp_commit(); \
    } while (0)

    TG_LOAD(0, 0);

    for (int c = 0; c < nch; c++) {
        const int s = c & 1;
        if (c + 1 < nch) { TG_LOAD(s ^ 1, c + 1); cp_wait1(); }
        else             { cp_wait0(); }
        __syncthreads();

        const uint32_t sb  = sm0 + (uint32_t)s * STAGE_S;
        const uint32_t sAh = sb, sAl = sb + A_TILE;
        const uint32_t sBh = sb + 2 * A_TILE, sBl = sBh + B_TILE;

        #pragma unroll
        for (int ks = 0; ks < 2; ks++) {
            const uint32_t ko = ks * 32;
            uint32_t bh[8][2], bl[8][2], af[4][4];
            #pragma unroll
            for (int p = 0; p < 4; p++) {
                uint32_t r[4];
                ldsm4(r, sBh + (uint32_t)(wncol + p * 16) * LDR + ko + b_off);
                bh[2 * p][0] = r[0]; bh[2 * p][1] = r[1];
                bh[2 * p + 1][0] = r[2]; bh[2 * p + 1][1] = r[3];
            }
            #pragma unroll
            for (int mt = 0; mt < 4; mt++)
                ldsm4(af[mt], sAh + (uint32_t)(wm * 64 + mt * 16) * LDR + ko + a_off);
            #pragma unroll
            for (int mt = 0; mt < 4; mt++)
                #pragma unroll
                for (int nt = 0; nt < 8; nt++) mma_bf16(acc[mt][nt], af[mt], bh[nt]);
            #pragma unroll
            for (int p = 0; p < 4; p++) {
                uint32_t r[4];
                ldsm4(r, sBl + (uint32_t)(wncol + p * 16) * LDR + ko + b_off);
                bl[2 * p][0] = r[0]; bl[2 * p][1] = r[1];
                bl[2 * p + 1][0] = r[2]; bl[2 * p + 1][1] = r[3];
            }
            #pragma unroll
            for (int mt = 0; mt < 4; mt++)
                #pragma unroll
                for (int nt = 0; nt < 8; nt++) mma_bf16(acc[mt][nt], af[mt], bl[nt]);
            #pragma unroll
            for (int mt = 0; mt < 4; mt++)
                ldsm4(af[mt], sAl + (uint32_t)(wm * 64 + mt * 16) * LDR + ko + a_off);
            #pragma unroll
            for (int mt = 0; mt < 4; mt++)
                #pragma unroll
                for (int nt = 0; nt < 8; nt++) mma_bf16(acc[mt][nt], af[mt], bh[nt]);
        }
        __syncthreads();
    }

    // epilogue
    #pragma unroll
    for (int mt = 0; mt < 4; mt++) {
        #pragma unroll
        for (int h = 0; h < 2; h++) {
            const int row = m0 + wm * 64 + mt * 16 + (lane >> 2) + h * 8;
            #pragma unroll
            for (int nt = 0; nt < 8; nt++) {
                const int col = n0 + wncol + nt * 8 + (lane & 3) * 2;
                float v0 = acc[mt][nt][h * 2 + 0];
                float v1 = acc[mt][nt][h * 2 + 1];
                if (flags & F_BCOL) { v0 += bias[col]; v1 += bias[col + 1]; }
                const size_t idx = (size_t)row * ldc + col;
                if (flags & F_SPLIT) {
                    __nv_bfloat16 h0 = __float2bfloat16_rn(v0);
                    __nv_bfloat16 h1 = __float2bfloat16_rn(v1);
                    __nv_bfloat16 l0 = __float2bfloat16_rn(v0 - __bfloat162float(h0));
                    __nv_bfloat16 l1 = __float2bfloat16_rn(v1 - __bfloat162float(h1));
                    uint32_t hp = (uint32_t)__bfloat16_as_ushort(h0) | ((uint32_t)__bfloat16_as_ushort(h1) << 16);
                    uint32_t lp = (uint32_t)__bfloat16_as_ushort(l0) | ((uint32_t)__bfloat16_as_ushort(l1) << 16);
                    *(uint32_t*)(Chi + (size_t)bz * sC + idx) = hp;
                    *(uint32_t*)(Clo + (size_t)bz * sC + idx) = lp;
                } else {
                    float2 o;
                    o.x = v0;
                    o.y = v1;
                    *(float2*)(Cf + (size_t)bz * sC + idx) = o;
                }
            }
        }
    }
}

// ---------------------------------------------------------------------------
// f16 GEMM, TWO=1: D = (Ah+Al).B^T (2 passes); TWO=0: D = Ah.B^T (1 pass).
// f32 accumulators. CTA 128x256, warp 64x64.
// ---------------------------------------------------------------------------
template <int TWO>
__global__ void __launch_bounds__(256, 1)
tgemm_h(const __half* __restrict__ Ah, const __half* __restrict__ Al,
        const __half* __restrict__ Bs,
        float* __restrict__ Cf, __half* __restrict__ Ch,
        const float* __restrict__ bias, const float* __restrict__ R,
        const float* __restrict__ gammap,
        int Kd, int ldc, size_t sA, size_t sB, size_t sC, size_t sR, int flags)
{
    constexpr int H_STAGE = (TWO ? 2 : 1) * A_TILE + B_TILE;
    extern __shared__ char smem[];
    const uint32_t sm0 = smem_to_u32(smem);
    const int tid = threadIdx.x, wid = tid >> 5, lane = tid & 31;
    const int bz = blockIdx.z;
    const int m0 = blockIdx.y * 128;
    const int n0 = blockIdx.x * 256;

    const size_t ldkB = (size_t)Kd * 2;
    const int lr = tid >> 2, seg = tid & 3;
    const char* gA_h = (const char*)(Ah + (size_t)bz * sA) + (size_t)(m0 + lr) * ldkB + seg * 16;
    const char* gA_l = TWO ? (const char*)(Al + (size_t)bz * sA) + (size_t)(m0 + lr) * ldkB + seg * 16 : nullptr;
    const char* gB   = (const char*)(Bs + (size_t)bz * sB) + (size_t)(n0 + lr) * ldkB + seg * 16;
    const size_t g64 = 64 * ldkB;
    const uint32_t dthr = sm0 + (uint32_t)lr * LDR + (uint32_t)seg * 16;
    const uint32_t boff_b = (TWO ? 2 : 1) * A_TILE;

    const int nch = Kd >> 5;
    const int wm = wid & 1;
    const int wncol = (wid >> 1) * 64;
    const uint32_t a_off = (uint32_t)((lane & 15) * LDR + (lane >> 4) * 16);
    const uint32_t b_off = (uint32_t)(((lane & 7) + ((lane >> 4) & 1) * 8) * LDR + ((lane >> 3) & 1) * 16);

    float acc[4][8][4];
    #pragma unroll
    for (int i = 0; i < 4; i++)
        #pragma unroll
        for (int j = 0; j < 8; j++)
            #pragma unroll
            for (int k = 0; k < 4; k++) acc[i][j][k] = 0.f;

#define TH_LOAD(s, c) do { \
        const size_t _ko = (size_t)(c) * 64; \
        const uint32_t _d = dthr + (uint32_t)(s) * H_STAGE; \
        cp16(_d,            gA_h + _ko); \
        cp16(_d + 64 * LDR, gA_h + _ko + g64); \
        if (TWO) { \
            cp16(_d + A_TILE,            gA_l + _ko); \
            cp16(_d + A_TILE + 64 * LDR, gA_l + _ko + g64); \
        } \
        _Pragma("unroll") \
        for (int _j = 0; _j < 4; _j++) \
            cp16(_d + boff_b + _j * 64 * LDR, gB + _ko + _j * g64); \
        cp_commit(); \
    } while (0)

    TH_LOAD(0, 0);

    for (int c = 0; c < nch; c++) {
        const int s = c & 1;
        if (c + 1 < nch) { TH_LOAD(s ^ 1, c + 1); cp_wait1(); }
        else             { cp_wait0(); }
        __syncthreads();

        const uint32_t sb  = sm0 + (uint32_t)s * H_STAGE;
        const uint32_t sAh = sb, sAl = sb + A_TILE, sB_ = sb + boff_b;

        #pragma unroll
        for (int ks = 0; ks < 2; ks++) {
            const uint32_t ko = ks * 32;
            uint32_t bf[8][2], af[4][4];
            #pragma unroll
            for (int p = 0; p < 4; p++) {
                uint32_t r[4];
                ldsm4(r, sB_ + (uint32_t)(wncol + p * 16) * LDR + ko + b_off);
                bf[2 * p][0] = r[0]; bf[2 * p][1] = r[1];
                bf[2 * p + 1][0] = r[2]; bf[2 * p + 1][1] = r[3];
            }
            #pragma unroll
            for (int mt = 0; mt < 4; mt++)
                ldsm4(af[mt], sAh + (uint32_t)(wm * 64 + mt * 16) * LDR + ko + a_off);
            #pragma unroll
            for (int mt = 0; mt < 4; mt++)
                #pragma unroll
                for (int nt = 0; nt < 8; nt++) mma_f16(acc[mt][nt], af[mt], bf[nt]);
            if (TWO) {
                #pragma unroll
                for (int mt = 0; mt < 4; mt++)
                    ldsm4(af[mt], sAl + (uint32_t)(wm * 64 + mt * 16) * LDR + ko + a_off);
                #pragma unroll
                for (int mt = 0; mt < 4; mt++)
                    #pragma unroll
                    for (int nt = 0; nt < 8; nt++) mma_f16(acc[mt][nt], af[mt], bf[nt]);
            }
        }
        __syncthreads();
    }

    if (flags & F_RES) {
        const float g = *gammap;
        #pragma unroll
        for (int mt = 0; mt < 4; mt++)
            #pragma unroll
            for (int h = 0; h < 2; h++) {
                const int row = m0 + wm * 64 + mt * 16 + (lane >> 2) + h * 8;
                #pragma unroll
                for (int nt = 0; nt < 8; nt++) {
                    const int col = n0 + wncol + nt * 8 + (lane & 3) * 2;
                    const size_t idx = (size_t)row * ldc + col;
                    const float2 rv = *(const float2*)(R + (size_t)bz * sR + idx);
                    float2 o;
                    o.x = g * acc[mt][nt][h * 2 + 0] + rv.x;
                    o.y = g * acc[mt][nt][h * 2 + 1] + rv.y;
                    *(float2*)(Cf + (size_t)bz * sC + idx) = o;
                }
            }
    } else {
        #pragma unroll
        for (int mt = 0; mt < 4; mt++)
            #pragma unroll
            for (int h = 0; h < 2; h++) {
                const int row = m0 + wm * 64 + mt * 16 + (lane >> 2) + h * 8;
                const float br = (flags & F_BROW) ? bias[row] : 0.f;
                #pragma unroll
                for (int nt = 0; nt < 8; nt++) {
                    const int col = n0 + wncol + nt * 8 + (lane & 3) * 2;
                    const size_t idx = (size_t)row * ldc + col;
                    __half2 p2 = __floats2half2_rn(acc[mt][nt][h * 2 + 0] + br,
                                                   acc[mt][nt][h * 2 + 1] + br);
                    *(uint32_t*)(Ch + (size_t)bz * sC + idx) = *(uint32_t*)&p2;
                }
            }
    }
}

// ---------------------------------------------------------------------------
// fused weight prep: Wq/Wk -> bf16 hi/lo, Wv -> single f16
// ---------------------------------------------------------------------------
__global__ void prep_split(const float* __restrict__ Wq, const float* __restrict__ Wk,
                           const float* __restrict__ Wv,
                           __nv_bfloat16* __restrict__ Wq_h, __nv_bfloat16* __restrict__ Wq_l,
                           __nv_bfloat16* __restrict__ Wk_h, __nv_bfloat16* __restrict__ Wk_l,
                           __half* __restrict__ Wv_f)
{
    const int i = blockIdx.x * blockDim.x + threadIdx.x;
    const int nqk = 256 * 512;
    if (i < 2 * nqk) {
        const float* src = (i < nqk) ? Wq : Wk;
        __nv_bfloat16* H = (i < nqk) ? Wq_h : Wk_h;
        __nv_bfloat16* L = (i < nqk) ? Wq_l : Wk_l;
        const int j = (i < nqk) ? i : i - nqk;
        const float v = src[j];
        const __nv_bfloat16 h = __float2bfloat16_rn(v);
        H[j] = h;
        L[j] = __float2bfloat16_rn(v - __bfloat162float(h));
    } else if (i < 2 * nqk + 512 * 512) {
        const int j = i - 2 * nqk;
        Wv_f[j] = __float2half_rn(Wv[j]);
    }
}

// ---------------------------------------------------------------------------
// fused transpose: Q,K -> bf16 hi/lo [N][C]; V -> single f16 [N][C]
// ---------------------------------------------------------------------------
__global__ __launch_bounds__(256)
void transpose_all(const float* __restrict__ Q, const float* __restrict__ Kin,
                   const float* __restrict__ V,
                   __nv_bfloat16* __restrict__ Qh, __nv_bfloat16* __restrict__ Ql,
                   __nv_bfloat16* __restrict__ Kh, __nv_bfloat16* __restrict__ Kl,
                   __half* __restrict__ Vt,
                   int rows, int cols, int batch)
{
    __shared__ float t[32][33];
    const int z = blockIdx.z;
    const int tsel = z / batch, bz = z % batch;
    const float* X = (tsel == 0) ? Q : (tsel == 1) ? Kin : V;
    const size_t bo = (size_t)bz * rows * cols;
    X += bo;
    const int x0 = blockIdx.x * 32;
    const int y0 = blockIdx.y * 32;
    const int tx = threadIdx.x & 31, ty = threadIdx.x >> 5;

    #pragma unroll
    for (int j = 0; j < 32; j += 8)
        t[ty + j][tx] = X[(size_t)(y0 + ty + j) * cols + x0 + tx];
    __syncthreads();

    if (tsel < 2) {
        __nv_bfloat16* Th = ((tsel == 0) ? Qh : Kh) + bo;
        __nv_bfloat16* Tl = ((tsel == 0) ? Ql : Kl) + bo;
        #pragma unroll
        for (int j = 0; j < 32; j += 8) {
            const float v = t[tx][ty + j];
            const __nv_bfloat16 h = __float2bfloat16_rn(v);
            const __nv_bfloat16 l = __float2bfloat16_rn(v - __bfloat162float(h));
            const size_t idx = (size_t)(x0 + ty + j) * rows + y0 + tx;
            Th[idx] = h;
            Tl[idx] = l;
        }
    } else {
        __half* Tv = Vt + bo;
        #pragma unroll
        for (int j = 0; j < 32; j += 8) {
            const size_t idx = (size_t)(x0 + ty + j) * rows + y0 + tx;
            Tv[idx] = __float2half_rn(t[tx][ty + j]);
        }
    }
}

// ---------------------------------------------------------------------------
// row softmax: 128 threads/row, 32 elems/thread (MLP=8 float4 loads),
// poly exp2, attention stored single f16. E/A pre-offset per launch.
// ---------------------------------------------------------------------------
__device__ __forceinline__ float fexp(float x) {  // exp(x), x <= 0
    float t = fmaxf(x * 1.44269504f, -126.f);
    float fi = floorf(t);
    float f = t - fi;
    float p = 1.5465324e-4f;
    p = p * f + 1.3333558e-3f;
    p = p * f + 9.6181291e-3f;
    p = p * f + 5.5504109e-2f;
    p = p * f + 2.4022651e-1f;
    p = p * f + 6.9314718e-1f;
    p = p * f + 1.0f;
    return p * __int_as_float(((int)fi + 127) << 23);
}

__global__ __launch_bounds__(128)
void softmax_row(const float* __restrict__ E, __half* __restrict__ A, int Ncols)
{
    const int row = blockIdx.x;
    const size_t base = (size_t)row * Ncols;
    const int tid = threadIdx.x, wid = tid >> 5, lid = tid & 31;

    __shared__ float sbuf[4];

    float x[32];
    const float4* rp = (const float4*)(E + base);
    #pragma unroll
    for (int k = 0; k < 8; k++) {
        float4 v4 = rp[tid + k * 128];
        x[k * 4 + 0] = v4.x; x[k * 4 + 1] = v4.y;
        x[k * 4 + 2] = v4.z; x[k * 4 + 3] = v4.w;
    }

    float m = x[0];
    #pragma unroll
    for (int i = 1; i < 32; i++) m = fmaxf(m, x[i]);
    #pragma unroll
    for (int o = 16; o; o >>= 1) m = fmaxf(m, __shfl_xor_sync(0xffffffffu, m, o));
    if (lid == 0) sbuf[wid] = m;
    __syncthreads();
    float mx = fmaxf(fmaxf(sbuf[0], sbuf[1]), fmaxf(sbuf[2], sbuf[3]));
    __syncthreads();

    float s = 0.f;
    #pragma unroll
    for (int i = 0; i < 32; i++) { x[i] = fexp(x[i] - mx); s += x[i]; }
    #pragma unroll
    for (int o = 16; o; o >>= 1) s += __shfl_xor_sync(0xffffffffu, s, o);
    if (lid == 0) sbuf[wid] = s;
    __syncthreads();
    const float tot = sbuf[0] + sbuf[1] + sbuf[2] + sbuf[3];
    const float inv = 1.f / tot;

    #pragma unroll
    for (int k = 0; k < 8; k++) {
        uint32_t hp[2];
        #pragma unroll
        for (int j = 0; j < 2; j++) {
            __half2 p2 = __floats2half2_rn(x[k * 4 + 2 * j] * inv, x[k * 4 + 2 * j + 1] * inv);
            hp[j] = *(uint32_t*)&p2;
        }
        const size_t idx = base + (size_t)(tid + k * 128) * 4;
        *(uint2*)(A + idx) = *(const uint2*)hp;
    }
}

// ---------------------------------------------------------------------------
extern "C" void kernel_launch(void* const* d_in, const int* in_sizes, int n_in,
                              void* d_out, int out_size)
{
    const float* Q     = (const float*)d_in[0];
    const float* Kin   = (const float*)d_in[1];
    const float* V     = (const float*)d_in[2];
    const float* Wq    = (const float*)d_in[3];
    const float* bq    = (const float*)d_in[4];
    const float* Wk    = (const float*)d_in[5];
    const float* bk    = (const float*)d_in[6];
    const float* Wv    = (const float*)d_in[7];
    const float* bv    = (const float*)d_in[8];
    const float* gamma = (const float*)d_in[9];
    float* out = (float*)d_out;

    __nv_bfloat16 *Qt_h, *Qt_l, *Kt_h, *Kt_l;
    __half *Vt, *Wv_f, *v, *a;
    __nv_bfloat16 *Wq_h, *Wq_l, *Wk_h, *Wk_l;
    __nv_bfloat16 *qt_h, *qt_l, *kt_h, *kt_l;
    float* e;
    cudaGetSymbolAddress((void**)&Qt_h, g_Qt_h); cudaGetSymbolAddress((void**)&Qt_l, g_Qt_l);
    cudaGetSymbolAddress((void**)&Kt_h, g_Kt_h); cudaGetSymbolAddress((void**)&Kt_l, g_Kt_l);
    cudaGetSymbolAddress((void**)&Vt,   g_Vt);
    cudaGetSymbolAddress((void**)&Wq_h, g_Wq_h); cudaGetSymbolAddress((void**)&Wq_l, g_Wq_l);
    cudaGetSymbolAddress((void**)&Wk_h, g_Wk_h); cudaGetSymbolAddress((void**)&Wk_l, g_Wk_l);
    cudaGetSymbolAddress((void**)&Wv_f, g_Wv);
    cudaGetSymbolAddress((void**)&qt_h, g_qt_h); cudaGetSymbolAddress((void**)&qt_l, g_qt_l);
    cudaGetSymbolAddress((void**)&kt_h, g_kt_h); cudaGetSymbolAddress((void**)&kt_l, g_kt_l);
    cudaGetSymbolAddress((void**)&v,    g_v);
    cudaGetSymbolAddress((void**)&a,    g_a);
    cudaGetSymbolAddress((void**)&e,    g_e);

    const int B = B_, C = C_, CH = CH_, N = N_;
    const size_t NN = (size_t)N * N;
    const size_t CN = (size_t)C * N;
    const size_t NC = (size_t)N * CH;

    // one-time host-side stream/event creation (no device memory involved)
    static cudaStream_t s2 = nullptr;
    static cudaEvent_t evT, evE01, evE23, evS01, evS23;
    if (!s2) {
        cudaStreamCreateWithFlags(&s2, cudaStreamNonBlocking);
        cudaEventCreateWithFlags(&evT,   cudaEventDisableTiming);
        cudaEventCreateWithFlags(&evE01, cudaEventDisableTiming);
        cudaEventCreateWithFlags(&evE23, cudaEventDisableTiming);
        cudaEventCreateWithFlags(&evS01, cudaEventDisableTiming);
        cudaEventCreateWithFlags(&evS23, cudaEventDisableTiming);
    }

    cudaFuncSetAttribute(tgemm_kernel, cudaFuncAttributeMaxDynamicSharedMemorySize, TG_SMEM);
    cudaFuncSetAttribute(tgemm_h<0>, cudaFuncAttributeMaxDynamicSharedMemorySize,
                         2 * (A_TILE + B_TILE));
    const int h0_smem = 2 * (A_TILE + B_TILE);

    // ---- main: weight prep + input transpose ----
    const int nsplit = 2 * CH * C + C * C;
    prep_split<<<(nsplit + 255) / 256, 256>>>(Wq, Wk, Wv, Wq_h, Wq_l, Wk_h, Wk_l, Wv_f);
    transpose_all<<<dim3(N / 32, C / 32, 3 * B), 256>>>(
        Q, Kin, V, Qt_h, Qt_l, Kt_h, Kt_l, Vt, C, N, B);

    // fork s2 after transpose
    cudaEventRecord(evT, 0);
    cudaStreamWaitEvent(s2, evT, 0);

    // ---- s2: v projection (independent of q/k; fills idle SMs) ----
    tgemm_h<0><<<dim3(N / 256, C / 128, B), 256, h0_smem, s2>>>(
        Wv_f, nullptr, Vt, nullptr, v, bv, nullptr, nullptr,
        C, N, 0, (size_t)N * C, CN, 0, F_BROW);

    // ---- main: q, k projections (bf16 split-3) ----
    tgemm_kernel<<<dim3(CH / 256, N / 128, B), 256, TG_SMEM>>>(
        Qt_h, Qt_l, Wq_h, Wq_l, nullptr, qt_h, qt_l, bq,
        C, CH, (size_t)N * C, 0, NC, F_SPLIT | F_BCOL);
    tgemm_kernel<<<dim3(CH / 256, N / 128, B), 256, TG_SMEM>>>(
        Kt_h, Kt_l, Wk_h, Wk_l, nullptr, kt_h, kt_l, bk,
        C, CH, (size_t)N * C, 0, NC, F_SPLIT | F_BCOL);

    // ---- main: energy in two half-batch launches (earlier softmax start) ----
    tgemm_kernel<<<dim3(N / 256, N / 128, 2), 256, TG_SMEM>>>(
        qt_h, qt_l, kt_h, kt_l, e, nullptr, nullptr, nullptr,
        CH, N, NC, NC, NN, 0);
    cudaEventRecord(evE01, 0);
    tgemm_kernel<<<dim3(N / 256, N / 128, 2), 256, TG_SMEM>>>(
        qt_h + 2 * NC, qt_l + 2 * NC, kt_h + 2 * NC, kt_l + 2 * NC,
        e + 2 * NN, nullptr, nullptr, nullptr,
        CH, N, NC, NC, NN, 0);
    cudaEventRecord(evE23, 0);

    // ---- s2: per-batch softmax (starts during E23 / out waves) ----
    cudaStreamWaitEvent(s2, evE01, 0);
    softmax_row<<<dim3(N, 1), 128, 0, s2>>>(e + 0 * NN, a + 0 * NN, N);
    softmax_row<<<dim3(N, 1), 128, 0, s2>>>(e + 1 * NN, a + 1 * NN, N);
    cudaEventRecord(evS01, s2);
    cudaStreamWaitEvent(s2, evE23, 0);
    softmax_row<<<dim3(N, 1), 128, 0, s2>>>(e + 2 * NN, a + 2 * NN, N);
    softmax_row<<<dim3(N, 1), 128, 0, s2>>>(e + 3 * NN, a + 3 * NN, N);
    cudaEventRecord(evS23, s2);

    // ---- main: out in two batch-pair launches ----
    cudaStreamWaitEvent(0, evS01, 0);
    tgemm_h<0><<<dim3(N / 256, C / 128, 2), 256, h0_smem>>>(
        v, nullptr, a, out, nullptr, nullptr, V, gamma,
        N, N, CN, NN, CN, CN, F_RES);
    cudaStreamWaitEvent(0, evS23, 0);
    tgemm_h<0><<<dim3(N / 256, C / 128, 2), 256, h0_smem>>>(
        v + 2 * CN, nullptr, a + 2 * NN, out + 2 * CN, nullptr, nullptr,
        V + 2 * CN, gamma,
        N, N, CN, NN, CN, CN, F_RES);
}